// round 11
// baseline (speedup 1.0000x reference)
#include <cuda_runtime.h>
#include <cuda_bf16.h>
#include <math.h>
#include <stdint.h>

#define D_MODEL 1024
#define D3      3072
#define NSEQ    4096
#define HEADS   16
#define DH      64

// Scratch (allocation-free rule: __device__ globals)
__device__ float g_qkv[NSEQ * D3];                  // fused q|k|v, stride 3072
__device__ __nv_bfloat16 g_xhi[NSEQ * D_MODEL];
__device__ __nv_bfloat16 g_xlo[NSEQ * D_MODEL];
__device__ __nv_bfloat16 g_qhi[NSEQ * D_MODEL];
__device__ __nv_bfloat16 g_qlo[NSEQ * D_MODEL];
__device__ __nv_bfloat16 g_khi[NSEQ * D_MODEL];
__device__ __nv_bfloat16 g_klo[NSEQ * D_MODEL];
__device__ __nv_bfloat16 g_vhi[NSEQ * D_MODEL];
__device__ __nv_bfloat16 g_vlo[NSEQ * D_MODEL];
__device__ __nv_bfloat16 g_ohi[NSEQ * D_MODEL];
__device__ __nv_bfloat16 g_olo[NSEQ * D_MODEL];
__device__ __nv_bfloat16 g_wh[D3 * D_MODEL];        // Wqkv^T hi [N][K] (concat)
__device__ __nv_bfloat16 g_wl[D3 * D_MODEL];        // Wqkv^T lo [N][K]
__device__ __nv_bfloat16 g_woh[D_MODEL * D_MODEL];  // Wo^T hi
__device__ __nv_bfloat16 g_wol[D_MODEL * D_MODEL];  // Wo^T lo

__device__ __forceinline__ uint32_t smem_u32(const void* p) {
    uint32_t a;
    asm("{ .reg .u64 t; cvta.to.shared.u64 t, %1; cvt.u32.u64 %0, t; }"
        : "=r"(a) : "l"(p));
    return a;
}

__device__ __forceinline__ void ldm4(uint32_t r[4], uint32_t addr) {
    asm volatile("ldmatrix.sync.aligned.m8n8.x4.shared.b16 {%0,%1,%2,%3}, [%4];"
                 : "=r"(r[0]), "=r"(r[1]), "=r"(r[2]), "=r"(r[3]) : "r"(addr));
}

__device__ __forceinline__ void ldm4t(uint32_t r[4], uint32_t addr) {
    asm volatile("ldmatrix.sync.aligned.m8n8.x4.trans.shared.b16 {%0,%1,%2,%3}, [%4];"
                 : "=r"(r[0]), "=r"(r[1]), "=r"(r[2]), "=r"(r[3]) : "r"(addr));
}

__device__ __forceinline__ void mma16816(float d[4], const uint32_t a[4],
                                         uint32_t b0, uint32_t b1) {
    asm volatile(
        "mma.sync.aligned.m16n8k16.row.col.f32.bf16.bf16.f32 "
        "{%0,%1,%2,%3}, {%4,%5,%6,%7}, {%8,%9}, {%0,%1,%2,%3};"
        : "+f"(d[0]), "+f"(d[1]), "+f"(d[2]), "+f"(d[3])
        : "r"(a[0]), "r"(a[1]), "r"(a[2]), "r"(a[3]), "r"(b0), "r"(b1));
}

__device__ __forceinline__ void cp16(uint32_t dst, const void* src) {
    asm volatile("cp.async.cg.shared.global [%0], [%1], 16;"
                 :: "r"(dst), "l"(src));
}

__device__ __forceinline__ uint32_t pkf(float x, float y) {
    __nv_bfloat162 h = __floats2bfloat162_rn(x, y);
    return *(uint32_t*)&h;
}

// ---------------------------------------------------------------------------
// split: fp32 -> (hi, lo) bf16, same layout. 4 elements / thread.
// ---------------------------------------------------------------------------
__global__ void split_kernel(const float* __restrict__ in,
                             __nv_bfloat16* __restrict__ hi,
                             __nv_bfloat16* __restrict__ lo)
{
    int i = blockIdx.x * blockDim.x + threadIdx.x;
    float4 v = ((const float4*)in)[i];
    __nv_bfloat16 h0 = __float2bfloat16(v.x), h1 = __float2bfloat16(v.y);
    __nv_bfloat16 h2 = __float2bfloat16(v.z), h3 = __float2bfloat16(v.w);
    float l0 = v.x - __bfloat162float(h0), l1 = v.y - __bfloat162float(h1);
    float l2 = v.z - __bfloat162float(h2), l3 = v.w - __bfloat162float(h3);
    __nv_bfloat162 hA = __halves2bfloat162(h0, h1), hB = __halves2bfloat162(h2, h3);
    ((uint2*)hi)[i] = make_uint2(*(uint32_t*)&hA, *(uint32_t*)&hB);
    ((uint2*)lo)[i] = make_uint2(pkf(l0, l1), pkf(l2, l3));
}

// ---------------------------------------------------------------------------
// fused transpose-convert of all 4 weights (z selects matrix).
// W[k][n] fp32 -> W^T hi/lo bf16 [n][k].
// ---------------------------------------------------------------------------
__global__ void tconv4_kernel(const float* __restrict__ Wq,
                              const float* __restrict__ Wk,
                              const float* __restrict__ Wv,
                              const float* __restrict__ Wo,
                              __nv_bfloat16* __restrict__ wh,
                              __nv_bfloat16* __restrict__ wl,
                              __nv_bfloat16* __restrict__ woh,
                              __nv_bfloat16* __restrict__ wol)
{
    __shared__ float tile[32][33];
    const int z = blockIdx.z;
    const float* W = (z == 0) ? Wq : (z == 1) ? Wk : (z == 2) ? Wv : Wo;
    __nv_bfloat16* dh = (z == 3) ? woh : wh + (size_t)z * D_MODEL * D_MODEL;
    __nv_bfloat16* dl = (z == 3) ? wol : wl + (size_t)z * D_MODEL * D_MODEL;

    const int n0 = blockIdx.x * 32, k0 = blockIdx.y * 32;
    const int tx = threadIdx.x, ty = threadIdx.y;   // 32 x 8
    #pragma unroll
    for (int j = 0; j < 4; j++)
        tile[ty + 8 * j][tx] = W[(size_t)(k0 + ty + 8 * j) * D_MODEL + n0 + tx];
    __syncthreads();
    #pragma unroll
    for (int j = 0; j < 4; j++) {
        float v = tile[tx][ty + 8 * j];
        __nv_bfloat16 h = __float2bfloat16(v);
        __nv_bfloat16 l = __float2bfloat16(v - __bfloat162float(h));
        size_t o = (size_t)(n0 + ty + 8 * j) * D_MODEL + k0 + tx;
        dh[o] = h;
        dl[o] = l;
    }
}

// ---------------------------------------------------------------------------
// Pipelined split-bf16 GEMM.  C[M,N] = A[M,K] @ B[K,N].  CTA 128x128, BK=16,
// 8 warps (2x4, warp tile 64x32), 3-stage cp.async, one barrier/iter,
// 2 CTAs/SM (launch_bounds caps regs at 128).
// ---------------------------------------------------------------------------
#define KSTR 24                               // smem row stride in halves
#define MAT_B (128 * KSTR * 2)                // 6144 bytes per matrix per stage
#define STG_B (4 * MAT_B)                     // 24576
#define GSMEM (3 * STG_B)                     // 73728

__global__ __launch_bounds__(256, 2) void gemm_tc4(
    const __nv_bfloat16* __restrict__ Ahi, const __nv_bfloat16* __restrict__ Alo,
    const __nv_bfloat16* __restrict__ BhiT, const __nv_bfloat16* __restrict__ BloT,
    float* __restrict__ C, int M, int N, int K)
{
    extern __shared__ __align__(16) __nv_bfloat16 smg[];
    const uint32_t sb = smem_u32(smg);
    const int t = threadIdx.x;
    const int wid = t >> 5, lane = t & 31;
    const int row0 = blockIdx.y * 128, col0 = blockIdx.x * 128;
    const int wm = (wid >> 2) * 64;    // 0 / 64
    const int wn = (wid & 3) * 32;     // 0..96

    const int r_c = t >> 1, c_c = t & 1;   // cp.async: row, 16B-chunk

    float acc[4][4][4];
    #pragma unroll
    for (int i = 0; i < 4; i++)
        #pragma unroll
        for (int j = 0; j < 4; j++)
            #pragma unroll
            for (int q = 0; q < 4; q++) acc[i][j][q] = 0.f;

    auto issue = [&](int stage, int k0) {
        uint32_t s0 = sb + (uint32_t)(stage * STG_B);
        uint32_t o  = (uint32_t)(r_c * (KSTR * 2) + c_c * 16);
        const size_t ga = (size_t)(row0 + r_c) * K + k0 + c_c * 8;
        const size_t gb = (size_t)(col0 + r_c) * K + k0 + c_c * 8;
        cp16(s0 + o,             Ahi + ga);
        cp16(s0 + MAT_B + o,     Alo + ga);
        cp16(s0 + 2 * MAT_B + o, BhiT + gb);
        cp16(s0 + 3 * MAT_B + o, BloT + gb);
        asm volatile("cp.async.commit_group;");
    };

    issue(0, 0);
    issue(1, 16);

    const int a_row = (lane & 7) + (lane & 8);
    const int a_col = (lane >> 4) << 3;
    const int b_row = (lane & 7) + ((lane & 16) >> 1);
    const int b_col = lane & 8;

    const int NIT = K >> 4;          // 64
    int stage = 0;
    for (int it = 0; it < NIT; it++) {
        asm volatile("cp.async.wait_group 1;");
        __syncthreads();

        const uint32_t s0 = sb + (uint32_t)(stage * STG_B);
        const uint32_t sAh = s0;
        const uint32_t sAl = s0 + MAT_B;
        const uint32_t sBh = s0 + 2 * MAT_B;
        const uint32_t sBl = s0 + 3 * MAT_B;

        // B fragments for the warp's 32 columns (2 n-tiles), hi+lo
        uint32_t bh[2][4], bl[2][4];
        #pragma unroll
        for (int p = 0; p < 2; p++) {
            uint32_t off = (uint32_t)(((wn + p * 16 + b_row) * KSTR + b_col) * 2);
            ldm4(bh[p], sBh + off);
            ldm4(bl[p], sBl + off);
        }

        #pragma unroll
        for (int mt = 0; mt < 4; mt++) {
            uint32_t ah[4], al[4];
            uint32_t off = (uint32_t)(((wm + mt * 16 + a_row) * KSTR + a_col) * 2);
            ldm4(ah, sAh + off);
            ldm4(al, sAl + off);
            #pragma unroll
            for (int nt = 0; nt < 4; nt++) {
                int p = nt >> 1, si = (nt & 1) * 2;
                mma16816(acc[mt][nt], ah, bh[p][si], bh[p][si + 1]);
                mma16816(acc[mt][nt], ah, bl[p][si], bl[p][si + 1]);
                mma16816(acc[mt][nt], al, bh[p][si], bh[p][si + 1]);
            }
        }

        if (it + 2 < NIT) {
            int ns = stage + 2;
            if (ns >= 3) ns -= 3;
            issue(ns, (it + 2) * 16);
        }
        stage = (stage + 1 == 3) ? 0 : stage + 1;
    }

    #pragma unroll
    for (int mt = 0; mt < 4; mt++)
        #pragma unroll
        for (int nt = 0; nt < 4; nt++) {
            int row = row0 + wm + mt * 16 + (lane >> 2);
            int col = col0 + wn + nt * 8 + (lane & 3) * 2;
            *(float2*)(C + (size_t)row * N + col) =
                make_float2(acc[mt][nt][0], acc[mt][nt][1]);
            *(float2*)(C + (size_t)(row + 8) * N + col) =
                make_float2(acc[mt][nt][2], acc[mt][nt][3]);
        }
}

// ---------------------------------------------------------------------------
// l2norm (q,k) + bf16 hi/lo split of q,k,v from the fused qkv buffer.
// ---------------------------------------------------------------------------
__global__ void l2split_kernel(const float* __restrict__ qkv,
                               __nv_bfloat16* __restrict__ qhi, __nv_bfloat16* __restrict__ qlo,
                               __nv_bfloat16* __restrict__ khi, __nv_bfloat16* __restrict__ klo,
                               __nv_bfloat16* __restrict__ vhi, __nv_bfloat16* __restrict__ vlo)
{
    int w    = (blockIdx.x * blockDim.x + threadIdx.x) >> 5;
    int lane = threadIdx.x & 31;
    int n    = w / 48;
    int slot = w % 48;
    const float* p = qkv + (size_t)n * D3 + slot * 64;
    float2 vv = ((const float2*)p)[lane];

    if (slot < 32) {
        float ss = vv.x * vv.x + vv.y * vv.y;
        #pragma unroll
        for (int off = 16; off; off >>= 1)
            ss += __shfl_xor_sync(0xffffffffu, ss, off);
        float s = 1.0f / fmaxf(sqrtf(ss), 1e-12f);
        vv.x *= s;
        vv.y *= s;
    }
    __nv_bfloat16 h0 = __float2bfloat16(vv.x), h1 = __float2bfloat16(vv.y);
    float l0 = vv.x - __bfloat162float(h0), l1 = vv.y - __bfloat162float(h1);
    __nv_bfloat162 hp = __halves2bfloat162(h0, h1);

    size_t d = ((size_t)n * D_MODEL + (slot & 15) * 64 + lane * 2) / 2;
    __nv_bfloat16* dh = (slot < 16) ? qhi : (slot < 32) ? khi : vhi;
    __nv_bfloat16* dl = (slot < 16) ? qlo : (slot < 32) ? klo : vlo;
    ((uint32_t*)dh)[d] = *(uint32_t*)&hp;
    ((uint32_t*)dl)[d] = pkf(l0, l1);
}

// ---------------------------------------------------------------------------
// Tensor-core flash attention (causal, scale=8). BM=64 (4 warps x m16),
// BN=64, DH=64, cp.async double-buffered K/V hi/lo, bf16-split everywhere.
// ---------------------------------------------------------------------------
#define VSTR 72
#define MATB (64 * VSTR * 2)          // bytes per matrix
#define FSTGB (4 * MATB)              // bytes per stage
#define FSMEM2 (2 * FSTGB)

__global__ __launch_bounds__(128) void flash_tc(
    const __nv_bfloat16* __restrict__ qhi, const __nv_bfloat16* __restrict__ qlo,
    const __nv_bfloat16* __restrict__ khi, const __nv_bfloat16* __restrict__ klo,
    const __nv_bfloat16* __restrict__ vhi, const __nv_bfloat16* __restrict__ vlo,
    __nv_bfloat16* __restrict__ ohi, __nv_bfloat16* __restrict__ olo)
{
    extern __shared__ __align__(16) __nv_bfloat16 smx[];
    const uint32_t sb = smem_u32(smx);
    const int qb = blockIdx.x, head = blockIdx.y;
    const int t = threadIdx.x, w = t >> 5, lane = t & 31;
    const int hcol = head * DH;

    const int lr = t >> 1, lh = (t & 1) * 32;

    auto ldstage = [&](uint32_t base, const __nv_bfloat16* mhi,
                       const __nv_bfloat16* mlo, int seq0) {
        const size_t g = (size_t)(seq0 + lr) * D_MODEL + hcol + lh;
        uint32_t d = base + (uint32_t)((lr * VSTR + lh) * 2);
        #pragma unroll
        for (int q2 = 0; q2 < 4; q2++) {
            cp16(d + q2 * 16,        mhi + g + q2 * 8);
            cp16(d + MATB + q2 * 16, mlo + g + q2 * 8);
        }
    };

    // ---- stage Q through stage-0 K slots, load A-fragments
    ldstage(sb, qhi, qlo, qb * 64);
    asm volatile("cp.async.commit_group;");
    asm volatile("cp.async.wait_group 0;");
    __syncthreads();

    const int a_row = (lane & 7) + (lane & 8);
    const int a_col = (lane >> 4) << 3;
    uint32_t ah[4][4], al[4][4];
    #pragma unroll
    for (int kc = 0; kc < 4; kc++) {
        uint32_t off = (uint32_t)(((w * 16 + a_row) * VSTR + kc * 16 + a_col) * 2);
        ldm4(ah[kc], sb + off);
        ldm4(al[kc], sb + MATB + off);
    }
    __syncthreads();

    auto issue = [&](int stage, int jb) {
        uint32_t s0 = sb + (uint32_t)(stage * FSTGB);
        ldstage(s0,            khi, klo, jb * 64);
        ldstage(s0 + 2 * MATB, vhi, vlo, jb * 64);
        asm volatile("cp.async.commit_group;");
    };
    issue(0, 0);
    if (qb >= 1) issue(1, 1);

    float o[8][4];
    #pragma unroll
    for (int i = 0; i < 8; i++)
        #pragma unroll
        for (int j = 0; j < 4; j++) o[i][j] = 0.f;
    float m0 = -1e30f, m1 = -1e30f, l0 = 0.f, l1 = 0.f;

    const int b_row = (lane & 7) + ((lane & 16) >> 1);
    const int b_col = lane & 8;
    const int vg = lane >> 3;
    const int v_row = (vg & 1) * 8 + (lane & 7);
    const int v_col = (vg >> 1) * 8;
    const int myrow0 = qb * 64 + w * 16 + (lane >> 2);

    for (int jb = 0; jb <= qb; jb++) {
        if (jb < qb) asm volatile("cp.async.wait_group 1;");
        else         asm volatile("cp.async.wait_group 0;");
        __syncthreads();

        const uint32_t s0 = sb + (uint32_t)((jb & 1) * FSTGB);
        const uint32_t pKh = s0, pKl = s0 + MATB;
        const uint32_t pVh = s0 + 2 * MATB, pVl = s0 + 3 * MATB;

        float s[8][4];
        #pragma unroll
        for (int i = 0; i < 8; i++)
            #pragma unroll
            for (int j = 0; j < 4; j++) s[i][j] = 0.f;

        #pragma unroll
        for (int kc = 0; kc < 4; kc++) {
            uint32_t bh[4][4], bl[4][4];
            #pragma unroll
            for (int p = 0; p < 4; p++) {
                uint32_t off = (uint32_t)(((p * 16 + b_row) * VSTR + kc * 16 + b_col) * 2);
                ldm4(bh[p], pKh + off);
                ldm4(bl[p], pKl + off);
            }
            #pragma unroll
            for (int nt = 0; nt < 8; nt++) {
                int p = nt >> 1, si = (nt & 1) * 2;
                mma16816(s[nt], ah[kc], bh[p][si], bh[p][si + 1]);
                mma16816(s[nt], ah[kc], bl[p][si], bl[p][si + 1]);
                mma16816(s[nt], al[kc], bh[p][si], bh[p][si + 1]);
            }
        }

        if (jb == qb) {
            #pragma unroll
            for (int nt = 0; nt < 8; nt++) {
                int colb = jb * 64 + nt * 8 + (lane & 3) * 2;
                #pragma unroll
                for (int c = 0; c < 4; c++) {
                    int col = colb + (c & 1);
                    int row = myrow0 + (c >> 1) * 8;
                    s[nt][c] = (col > row) ? -1e30f : s[nt][c] * 8.0f;
                }
            }
        } else {
            #pragma unroll
            for (int nt = 0; nt < 8; nt++)
                #pragma unroll
                for (int c = 0; c < 4; c++) s[nt][c] *= 8.0f;
        }

        float mx0 = -1e30f, mx1 = -1e30f;
        #pragma unroll
        for (int nt = 0; nt < 8; nt++) {
            mx0 = fmaxf(mx0, fmaxf(s[nt][0], s[nt][1]));
            mx1 = fmaxf(mx1, fmaxf(s[nt][2], s[nt][3]));
        }
        mx0 = fmaxf(mx0, __shfl_xor_sync(0xffffffffu, mx0, 1));
        mx0 = fmaxf(mx0, __shfl_xor_sync(0xffffffffu, mx0, 2));
        mx1 = fmaxf(mx1, __shfl_xor_sync(0xffffffffu, mx1, 1));
        mx1 = fmaxf(mx1, __shfl_xor_sync(0xffffffffu, mx1, 2));
        float mn0 = fmaxf(m0, mx0), mn1 = fmaxf(m1, mx1);
        float c0 = __expf(m0 - mn0), c1 = __expf(m1 - mn1);
        m0 = mn0; m1 = mn1;

        float rs0 = 0.f, rs1 = 0.f;
        #pragma unroll
        for (int nt = 0; nt < 8; nt++) {
            s[nt][0] = __expf(s[nt][0] - mn0);
            s[nt][1] = __expf(s[nt][1] - mn0);
            s[nt][2] = __expf(s[nt][2] - mn1);
            s[nt][3] = __expf(s[nt][3] - mn1);
            rs0 += s[nt][0] + s[nt][1];
            rs1 += s[nt][2] + s[nt][3];
        }
        rs0 += __shfl_xor_sync(0xffffffffu, rs0, 1);
        rs0 += __shfl_xor_sync(0xffffffffu, rs0, 2);
        rs1 += __shfl_xor_sync(0xffffffffu, rs1, 1);
        rs1 += __shfl_xor_sync(0xffffffffu, rs1, 2);
        l0 = l0 * c0 + rs0;
        l1 = l1 * c1 + rs1;
        #pragma unroll
        for (int nt = 0; nt < 8; nt++) {
            o[nt][0] *= c0; o[nt][1] *= c0;
            o[nt][2] *= c1; o[nt][3] *= c1;
        }

        #pragma unroll
        for (int kt = 0; kt < 4; kt++) {
            uint32_t pa_h[4], pa_l[4];
            #pragma unroll
            for (int hh = 0; hh < 2; hh++) {
                const float* sv = s[2 * kt + hh];
                __nv_bfloat16 h0 = __float2bfloat16(sv[0]);
                __nv_bfloat16 h1 = __float2bfloat16(sv[1]);
                __nv_bfloat16 h2 = __float2bfloat16(sv[2]);
                __nv_bfloat16 h3 = __float2bfloat16(sv[3]);
                __nv_bfloat162 p01 = __halves2bfloat162(h0, h1);
                __nv_bfloat162 p23 = __halves2bfloat162(h2, h3);
                pa_h[2 * hh]     = *(uint32_t*)&p01;
                pa_h[2 * hh + 1] = *(uint32_t*)&p23;
                pa_l[2 * hh]     = pkf(sv[0] - __bfloat162float(h0),
                                       sv[1] - __bfloat162float(h1));
                pa_l[2 * hh + 1] = pkf(sv[2] - __bfloat162float(h2),
                                       sv[3] - __bfloat162float(h3));
            }
            uint32_t afh[4] = {pa_h[0], pa_h[1], pa_h[2], pa_h[3]};
            uint32_t afl[4] = {pa_l[0], pa_l[1], pa_l[2], pa_l[3]};

            #pragma unroll
            for (int nc = 0; nc < 4; nc++) {
                uint32_t off = (uint32_t)(((kt * 16 + v_row) * VSTR + nc * 16 + v_col) * 2);
                uint32_t vbh[4], vbl[4];
                ldm4t(vbh, pVh + off);
                ldm4t(vbl, pVl + off);
                mma16816(o[2 * nc],     afh, vbh[0], vbh[1]);
                mma16816(o[2 * nc],     afh, vbl[0], vbl[1]);
                mma16816(o[2 * nc],     afl, vbh[0], vbh[1]);
                mma16816(o[2 * nc + 1], afh, vbh[2], vbh[3]);
                mma16816(o[2 * nc + 1], afh, vbl[2], vbl[3]);
                mma16816(o[2 * nc + 1], afl, vbh[2], vbh[3]);
            }
        }

        __syncthreads();
        if (jb + 2 <= qb) issue(jb & 1, jb + 2);
    }

    float inv0 = 1.0f / l0, inv1 = 1.0f / l1;
    #pragma unroll
    for (int nt = 0; nt < 8; nt++) {
        int col = hcol + nt * 8 + (lane & 3) * 2;
        {
            float x = o[nt][0] * inv0, y = o[nt][1] * inv0;
            __nv_bfloat16 hx = __float2bfloat16(x), hy = __float2bfloat16(y);
            __nv_bfloat162 hp = __halves2bfloat162(hx, hy);
            size_t d = ((size_t)myrow0 * D_MODEL + col) / 2;
            ((uint32_t*)ohi)[d] = *(uint32_t*)&hp;
            ((uint32_t*)olo)[d] = pkf(x - __bfloat162float(hx), y - __bfloat162float(hy));
        }
        {
            float x = o[nt][2] * inv1, y = o[nt][3] * inv1;
            __nv_bfloat16 hx = __float2bfloat16(x), hy = __float2bfloat16(y);
            __nv_bfloat162 hp = __halves2bfloat162(hx, hy);
            size_t d = ((size_t)(myrow0 + 8) * D_MODEL + col) / 2;
            ((uint32_t*)ohi)[d] = *(uint32_t*)&hp;
            ((uint32_t*)olo)[d] = pkf(x - __bfloat162float(hx), y - __bfloat162float(hy));
        }
    }
}

// ---------------------------------------------------------------------------
extern "C" void kernel_launch(void* const* d_in, const int* in_sizes, int n_in,
                              void* d_out, int out_size)
{
    const float* x  = (const float*)d_in[0];
    const float* Wq = (const float*)d_in[1];
    const float* Wk = (const float*)d_in[2];
    const float* Wv = (const float*)d_in[3];
    const float* Wo = (const float*)d_in[4];

    float* qkv;
    __nv_bfloat16 *xhi, *xlo, *qhi, *qlo, *khi, *klo, *vhi, *vlo, *ohi, *olo;
    __nv_bfloat16 *wh, *wl, *woh, *wol;
    cudaGetSymbolAddress((void**)&qkv, g_qkv);
    cudaGetSymbolAddress((void**)&xhi, g_xhi);
    cudaGetSymbolAddress((void**)&xlo, g_xlo);
    cudaGetSymbolAddress((void**)&qhi, g_qhi);
    cudaGetSymbolAddress((void**)&qlo, g_qlo);
    cudaGetSymbolAddress((void**)&khi, g_khi);
    cudaGetSymbolAddress((void**)&klo, g_klo);
    cudaGetSymbolAddress((void**)&vhi, g_vhi);
    cudaGetSymbolAddress((void**)&vlo, g_vlo);
    cudaGetSymbolAddress((void**)&ohi, g_ohi);
    cudaGetSymbolAddress((void**)&olo, g_olo);
    cudaGetSymbolAddress((void**)&wh, g_wh);
    cudaGetSymbolAddress((void**)&wl, g_wl);
    cudaGetSymbolAddress((void**)&woh, g_woh);
    cudaGetSymbolAddress((void**)&wol, g_wol);

    cudaFuncSetAttribute(gemm_tc4,
                         cudaFuncAttributeMaxDynamicSharedMemorySize, GSMEM);
    cudaFuncSetAttribute(flash_tc,
                         cudaFuncAttributeMaxDynamicSharedMemorySize, FSMEM2);

    const int NE4 = NSEQ * D_MODEL / 4;

    split_kernel<<<NE4 / 256, 256>>>(x, xhi, xlo);
    tconv4_kernel<<<dim3(D_MODEL / 32, D_MODEL / 32, 4), dim3(32, 8)>>>(
        Wq, Wk, Wv, Wo, wh, wl, woh, wol);

    gemm_tc4<<<dim3(D3 / 128, NSEQ / 128), 256, GSMEM>>>(
        xhi, xlo, wh, wl, qkv, NSEQ, D3, D_MODEL);

    l2split_kernel<<<NSEQ * 48 / 8, 256>>>(qkv, qhi, qlo, khi, klo, vhi, vlo);

    flash_tc<<<dim3(NSEQ / 64, HEADS), 128, FSMEM2>>>(
        qhi, qlo, khi, klo, vhi, vlo, ohi, olo);

    gemm_tc4<<<dim3(D_MODEL / 128, NSEQ / 128), 256, GSMEM>>>(
        ohi, olo, woh, wol, (float*)d_out, NSEQ, D_MODEL, D_MODEL);
}

// round 12
// speedup vs baseline: 1.6222x; 1.6222x over previous
#include <cuda_runtime.h>
#include <cuda_fp16.h>
#include <math.h>
#include <stdint.h>

#define D_MODEL 1024
#define D3      3072
#define NSEQ    4096
#define HEADS   16
#define DH      64

// Scratch (allocation-free rule: __device__ globals)
__device__ float g_qkv[NSEQ * D3];                  // fused q|k|v, stride 3072
__device__ __half g_xhi[NSEQ * D_MODEL];
__device__ __half g_xlo[NSEQ * D_MODEL];
__device__ __half g_qhi[NSEQ * D_MODEL];
__device__ __half g_qlo[NSEQ * D_MODEL];
__device__ __half g_kf [NSEQ * D_MODEL];
__device__ __half g_vf [NSEQ * D_MODEL];
__device__ __half g_ohi[NSEQ * D_MODEL];
__device__ __half g_olo[NSEQ * D_MODEL];
__device__ __half g_wf [D3 * D_MODEL];              // Wqkv^T fp16 [N][K] concat
__device__ __half g_wof[D_MODEL * D_MODEL];         // Wo^T fp16

__device__ __forceinline__ uint32_t smem_u32(const void* p) {
    uint32_t a;
    asm("{ .reg .u64 t; cvta.to.shared.u64 t, %1; cvt.u32.u64 %0, t; }"
        : "=r"(a) : "l"(p));
    return a;
}

__device__ __forceinline__ void ldm4(uint32_t r[4], uint32_t addr) {
    asm volatile("ldmatrix.sync.aligned.m8n8.x4.shared.b16 {%0,%1,%2,%3}, [%4];"
                 : "=r"(r[0]), "=r"(r[1]), "=r"(r[2]), "=r"(r[3]) : "r"(addr));
}

__device__ __forceinline__ void ldm4t(uint32_t r[4], uint32_t addr) {
    asm volatile("ldmatrix.sync.aligned.m8n8.x4.trans.shared.b16 {%0,%1,%2,%3}, [%4];"
                 : "=r"(r[0]), "=r"(r[1]), "=r"(r[2]), "=r"(r[3]) : "r"(addr));
}

__device__ __forceinline__ void mma16816(float d[4], const uint32_t a[4],
                                         uint32_t b0, uint32_t b1) {
    asm volatile(
        "mma.sync.aligned.m16n8k16.row.col.f32.f16.f16.f32 "
        "{%0,%1,%2,%3}, {%4,%5,%6,%7}, {%8,%9}, {%0,%1,%2,%3};"
        : "+f"(d[0]), "+f"(d[1]), "+f"(d[2]), "+f"(d[3])
        : "r"(a[0]), "r"(a[1]), "r"(a[2]), "r"(a[3]), "r"(b0), "r"(b1));
}

__device__ __forceinline__ void cp16(uint32_t dst, const void* src) {
    asm volatile("cp.async.cg.shared.global [%0], [%1], 16;"
                 :: "r"(dst), "l"(src));
}

__device__ __forceinline__ uint32_t pkh(float x, float y) {
    __half2 h = __floats2half2_rn(x, y);
    return *(uint32_t*)&h;
}

// ---------------------------------------------------------------------------
// split: fp32 -> (hi, lo) fp16, same layout. 4 elements / thread.
// ---------------------------------------------------------------------------
__global__ void split_kernel(const float* __restrict__ in,
                             __half* __restrict__ hi, __half* __restrict__ lo)
{
    int i = blockIdx.x * blockDim.x + threadIdx.x;
    float4 v = ((const float4*)in)[i];
    __half h0 = __float2half_rn(v.x), h1 = __float2half_rn(v.y);
    __half h2 = __float2half_rn(v.z), h3 = __float2half_rn(v.w);
    float l0 = v.x - __half2float(h0), l1 = v.y - __half2float(h1);
    float l2 = v.z - __half2float(h2), l3 = v.w - __half2float(h3);
    __half2 hA = __halves2half2(h0, h1), hB = __halves2half2(h2, h3);
    ((uint2*)hi)[i] = make_uint2(*(uint32_t*)&hA, *(uint32_t*)&hB);
    ((uint2*)lo)[i] = make_uint2(pkh(l0, l1), pkh(l2, l3));
}

// ---------------------------------------------------------------------------
// fused transpose-convert of all 4 weights (z selects matrix) to single fp16.
// ---------------------------------------------------------------------------
__global__ void tconv4_kernel(const float* __restrict__ Wq,
                              const float* __restrict__ Wk,
                              const float* __restrict__ Wv,
                              const float* __restrict__ Wo,
                              __half* __restrict__ wf, __half* __restrict__ wof)
{
    __shared__ float tile[32][33];
    const int z = blockIdx.z;
    const float* W = (z == 0) ? Wq : (z == 1) ? Wk : (z == 2) ? Wv : Wo;
    __half* dh = (z == 3) ? wof : wf + (size_t)z * D_MODEL * D_MODEL;

    const int n0 = blockIdx.x * 32, k0 = blockIdx.y * 32;
    const int tx = threadIdx.x, ty = threadIdx.y;   // 32 x 8
    #pragma unroll
    for (int j = 0; j < 4; j++)
        tile[ty + 8 * j][tx] = W[(size_t)(k0 + ty + 8 * j) * D_MODEL + n0 + tx];
    __syncthreads();
    #pragma unroll
    for (int j = 0; j < 4; j++) {
        float v = tile[tx][ty + 8 * j];
        dh[(size_t)(n0 + ty + 8 * j) * D_MODEL + k0 + tx] = __float2half_rn(v);
    }
}

// ---------------------------------------------------------------------------
// Pipelined 2-pass fp16 GEMM.  C[M,N] = (Ahi+Alo)[M][K] @ Bf^T[N][K].
// CTA 128x256, BK=32, 8 warps (2x4, warp tile 64x64), 3-stage cp.async.
// ---------------------------------------------------------------------------
#define ASTR 40
#define A_SZ (128 * ASTR * 2)                 // 10240 bytes per A matrix
#define B_SZ (256 * ASTR * 2)                 // 20480 bytes for Bf
#define STG_B (2 * A_SZ + B_SZ)               // 40960
#define GSMEM (3 * STG_B)                     // 122880

__global__ __launch_bounds__(256, 1) void gemm_fp16(
    const __half* __restrict__ Ahi, const __half* __restrict__ Alo,
    const __half* __restrict__ Bf,
    float* __restrict__ C, int M, int N, int K)
{
    extern __shared__ __align__(16) __half smg[];
    const uint32_t sb = smem_u32(smg);
    const int t = threadIdx.x;
    const int wid = t >> 5, lane = t & 31;
    const int row0 = blockIdx.y * 128, col0 = blockIdx.x * 256;
    const int wm = (wid >> 2) * 64;    // 0 / 64
    const int wn = (wid & 3) * 64;     // 0..192

    const int r_c = t >> 2, c_c = t & 3;   // cp.async coords

    float acc[4][8][4];
    #pragma unroll
    for (int i = 0; i < 4; i++)
        #pragma unroll
        for (int j = 0; j < 8; j++)
            #pragma unroll
            for (int q = 0; q < 4; q++) acc[i][j][q] = 0.f;

    auto issue = [&](int stage, int k0) {
        uint32_t s0 = sb + (uint32_t)(stage * STG_B);
        #pragma unroll
        for (int h = 0; h < 2; h++) {
            int r = r_c + h * 64;
            uint32_t o = (uint32_t)((r * ASTR + c_c * 8) * 2);
            const size_t g = (size_t)(row0 + r) * K + k0 + c_c * 8;
            cp16(s0 + o,        Ahi + g);
            cp16(s0 + A_SZ + o, Alo + g);
        }
        #pragma unroll
        for (int h = 0; h < 4; h++) {
            int r = r_c + h * 64;
            uint32_t o = (uint32_t)((r * ASTR + c_c * 8) * 2);
            const size_t g = (size_t)(col0 + r) * K + k0 + c_c * 8;
            cp16(s0 + 2 * A_SZ + o, Bf + g);
        }
        asm volatile("cp.async.commit_group;");
    };

    issue(0, 0);
    issue(1, 32);

    const int a_row = (lane & 7) + (lane & 8);
    const int a_col = (lane >> 4) << 3;
    const int b_row = (lane & 7) + ((lane & 16) >> 1);
    const int b_col = lane & 8;

    const int NIT = K >> 5;          // 32
    int stage = 0;
    for (int it = 0; it < NIT; it++) {
        asm volatile("cp.async.wait_group 1;");
        __syncthreads();

        const uint32_t s0 = sb + (uint32_t)(stage * STG_B);
        const uint32_t sAh = s0;
        const uint32_t sAl = s0 + A_SZ;
        const uint32_t sBf = s0 + 2 * A_SZ;

        #pragma unroll
        for (int ks = 0; ks < 2; ks++) {
            const int kb = ks * 16;
            uint32_t ah[4][4], al[4][4];
            #pragma unroll
            for (int mt = 0; mt < 4; mt++) {
                uint32_t off = (uint32_t)(((wm + mt * 16 + a_row) * ASTR + kb + a_col) * 2);
                ldm4(ah[mt], sAh + off);
                ldm4(al[mt], sAl + off);
            }
            #pragma unroll
            for (int p = 0; p < 4; p++) {
                uint32_t bf[4];
                uint32_t off = (uint32_t)(((wn + p * 16 + b_row) * ASTR + kb + b_col) * 2);
                ldm4(bf, sBf + off);
                #pragma unroll
                for (int mt = 0; mt < 4; mt++) {
                    #pragma unroll
                    for (int half = 0; half < 2; half++) {
                        int nt = p * 2 + half, si = half * 2;
                        mma16816(acc[mt][nt], ah[mt], bf[si], bf[si + 1]);
                        mma16816(acc[mt][nt], al[mt], bf[si], bf[si + 1]);
                    }
                }
            }
        }

        if (it + 2 < NIT) {
            int ns = stage + 2;
            if (ns >= 3) ns -= 3;
            issue(ns, (it + 2) * 32);
        }
        stage = (stage + 1 == 3) ? 0 : stage + 1;
    }

    #pragma unroll
    for (int mt = 0; mt < 4; mt++)
        #pragma unroll
        for (int nt = 0; nt < 8; nt++) {
            int row = row0 + wm + mt * 16 + (lane >> 2);
            int col = col0 + wn + nt * 8 + (lane & 3) * 2;
            *(float2*)(C + (size_t)row * N + col) =
                make_float2(acc[mt][nt][0], acc[mt][nt][1]);
            *(float2*)(C + (size_t)(row + 8) * N + col) =
                make_float2(acc[mt][nt][2], acc[mt][nt][3]);
        }
}

// ---------------------------------------------------------------------------
// l2norm (q,k) + fp16 conversions from the fused qkv buffer.
// q -> split (qhi,qlo); k -> single kf; v -> single vf.
// ---------------------------------------------------------------------------
__global__ void l2split_kernel(const float* __restrict__ qkv,
                               __half* __restrict__ qhi, __half* __restrict__ qlo,
                               __half* __restrict__ kf, __half* __restrict__ vf)
{
    int w    = (blockIdx.x * blockDim.x + threadIdx.x) >> 5;
    int lane = threadIdx.x & 31;
    int n    = w / 48;
    int slot = w % 48;
    const float* p = qkv + (size_t)n * D3 + slot * 64;
    float2 vv = ((const float2*)p)[lane];

    if (slot < 32) {
        float ss = vv.x * vv.x + vv.y * vv.y;
        #pragma unroll
        for (int off = 16; off; off >>= 1)
            ss += __shfl_xor_sync(0xffffffffu, ss, off);
        float s = 1.0f / fmaxf(sqrtf(ss), 1e-12f);
        vv.x *= s;
        vv.y *= s;
    }

    size_t d = ((size_t)n * D_MODEL + (slot & 15) * 64 + lane * 2) / 2;
    if (slot < 16) {
        __half h0 = __float2half_rn(vv.x), h1 = __float2half_rn(vv.y);
        float l0 = vv.x - __half2float(h0), l1 = vv.y - __half2float(h1);
        __half2 hp = __halves2half2(h0, h1);
        ((uint32_t*)qhi)[d] = *(uint32_t*)&hp;
        ((uint32_t*)qlo)[d] = pkh(l0, l1);
    } else {
        __half* dst = (slot < 32) ? kf : vf;
        ((uint32_t*)dst)[d] = pkh(vv.x, vv.y);
    }
}

// ---------------------------------------------------------------------------
// Tensor-core flash attention (causal, scale=8), 2-pass fp16.
// BM=64 (4 warps x m16), BN=64, DH=64.  Q split (exact), K/V rounded once.
// ---------------------------------------------------------------------------
#define VSTR 72
#define MATB (64 * VSTR * 2)          // 9216 bytes per matrix
#define FSTGB (2 * MATB)              // Kf + Vf per stage
#define FSMEM2 (2 * FSTGB)            // 36864

__global__ __launch_bounds__(128) void flash_tc(
    const __half* __restrict__ qhi, const __half* __restrict__ qlo,
    const __half* __restrict__ kf, const __half* __restrict__ vf,
    __half* __restrict__ ohi, __half* __restrict__ olo)
{
    extern __shared__ __align__(16) __half smx[];
    const uint32_t sb = smem_u32(smx);
    const int qb = blockIdx.x, head = blockIdx.y;
    const int t = threadIdx.x, w = t >> 5, lane = t & 31;
    const int hcol = head * DH;

    const int lr = t >> 1, lh = (t & 1) * 32;

    auto ldmat = [&](uint32_t base, const __half* m, int seq0) {
        const size_t g = (size_t)(seq0 + lr) * D_MODEL + hcol + lh;
        uint32_t d = base + (uint32_t)((lr * VSTR + lh) * 2);
        #pragma unroll
        for (int q2 = 0; q2 < 4; q2++)
            cp16(d + q2 * 16, m + g + q2 * 8);
    };

    // ---- stage Q hi/lo through stage-0 slots, extract A-fragments
    ldmat(sb, qhi, qb * 64);
    ldmat(sb + MATB, qlo, qb * 64);
    asm volatile("cp.async.commit_group;");
    asm volatile("cp.async.wait_group 0;");
    __syncthreads();

    const int a_row = (lane & 7) + (lane & 8);
    const int a_col = (lane >> 4) << 3;
    uint32_t ah[4][4], al[4][4];
    #pragma unroll
    for (int kc = 0; kc < 4; kc++) {
        uint32_t off = (uint32_t)(((w * 16 + a_row) * VSTR + kc * 16 + a_col) * 2);
        ldm4(ah[kc], sb + off);
        ldm4(al[kc], sb + MATB + off);
    }
    __syncthreads();

    auto issue = [&](int stage, int jb) {
        uint32_t s0 = sb + (uint32_t)(stage * FSTGB);
        ldmat(s0,        kf, jb * 64);
        ldmat(s0 + MATB, vf, jb * 64);
        asm volatile("cp.async.commit_group;");
    };
    issue(0, 0);
    if (qb >= 1) issue(1, 1);

    float o[8][4];
    #pragma unroll
    for (int i = 0; i < 8; i++)
        #pragma unroll
        for (int j = 0; j < 4; j++) o[i][j] = 0.f;
    float m0 = -1e30f, m1 = -1e30f, l0 = 0.f, l1 = 0.f;

    const int b_row = (lane & 7) + ((lane & 16) >> 1);
    const int b_col = lane & 8;
    const int vg = lane >> 3;
    const int v_row = (vg & 1) * 8 + (lane & 7);
    const int v_col = (vg >> 1) * 8;
    const int myrow0 = qb * 64 + w * 16 + (lane >> 2);

    for (int jb = 0; jb <= qb; jb++) {
        if (jb < qb) asm volatile("cp.async.wait_group 1;");
        else         asm volatile("cp.async.wait_group 0;");
        __syncthreads();

        const uint32_t s0 = sb + (uint32_t)((jb & 1) * FSTGB);
        const uint32_t pKf = s0, pVf = s0 + MATB;

        float s[8][4];
        #pragma unroll
        for (int i = 0; i < 8; i++)
            #pragma unroll
            for (int j = 0; j < 4; j++) s[i][j] = 0.f;

        #pragma unroll
        for (int kc = 0; kc < 4; kc++) {
            uint32_t bh[4][4];
            #pragma unroll
            for (int p = 0; p < 4; p++) {
                uint32_t off = (uint32_t)(((p * 16 + b_row) * VSTR + kc * 16 + b_col) * 2);
                ldm4(bh[p], pKf + off);
            }
            #pragma unroll
            for (int nt = 0; nt < 8; nt++) {
                int p = nt >> 1, si = (nt & 1) * 2;
                mma16816(s[nt], ah[kc], bh[p][si], bh[p][si + 1]);
                mma16816(s[nt], al[kc], bh[p][si], bh[p][si + 1]);
            }
        }

        if (jb == qb) {
            #pragma unroll
            for (int nt = 0; nt < 8; nt++) {
                int colb = jb * 64 + nt * 8 + (lane & 3) * 2;
                #pragma unroll
                for (int c = 0; c < 4; c++) {
                    int col = colb + (c & 1);
                    int row = myrow0 + (c >> 1) * 8;
                    s[nt][c] = (col > row) ? -1e30f : s[nt][c] * 8.0f;
                }
            }
        } else {
            #pragma unroll
            for (int nt = 0; nt < 8; nt++)
                #pragma unroll
                for (int c = 0; c < 4; c++) s[nt][c] *= 8.0f;
        }

        float mx0 = -1e30f, mx1 = -1e30f;
        #pragma unroll
        for (int nt = 0; nt < 8; nt++) {
            mx0 = fmaxf(mx0, fmaxf(s[nt][0], s[nt][1]));
            mx1 = fmaxf(mx1, fmaxf(s[nt][2], s[nt][3]));
        }
        mx0 = fmaxf(mx0, __shfl_xor_sync(0xffffffffu, mx0, 1));
        mx0 = fmaxf(mx0, __shfl_xor_sync(0xffffffffu, mx0, 2));
        mx1 = fmaxf(mx1, __shfl_xor_sync(0xffffffffu, mx1, 1));
        mx1 = fmaxf(mx1, __shfl_xor_sync(0xffffffffu, mx1, 2));
        float mn0 = fmaxf(m0, mx0), mn1 = fmaxf(m1, mx1);
        float c0 = __expf(m0 - mn0), c1 = __expf(m1 - mn1);
        m0 = mn0; m1 = mn1;

        float rs0 = 0.f, rs1 = 0.f;
        #pragma unroll
        for (int nt = 0; nt < 8; nt++) {
            s[nt][0] = __expf(s[nt][0] - mn0);
            s[nt][1] = __expf(s[nt][1] - mn0);
            s[nt][2] = __expf(s[nt][2] - mn1);
            s[nt][3] = __expf(s[nt][3] - mn1);
            rs0 += s[nt][0] + s[nt][1];
            rs1 += s[nt][2] + s[nt][3];
        }
        rs0 += __shfl_xor_sync(0xffffffffu, rs0, 1);
        rs0 += __shfl_xor_sync(0xffffffffu, rs0, 2);
        rs1 += __shfl_xor_sync(0xffffffffu, rs1, 1);
        rs1 += __shfl_xor_sync(0xffffffffu, rs1, 2);
        l0 = l0 * c0 + rs0;
        l1 = l1 * c1 + rs1;
        #pragma unroll
        for (int nt = 0; nt < 8; nt++) {
            o[nt][0] *= c0; o[nt][1] *= c0;
            o[nt][2] *= c1; o[nt][3] *= c1;
        }

        // ---- O += P V (2 passes): P split into fp16 hi/lo in regs, V single
        #pragma unroll
        for (int kt = 0; kt < 4; kt++) {
            uint32_t afh[4], afl[4];
            #pragma unroll
            for (int hh = 0; hh < 2; hh++) {
                const float* sv = s[2 * kt + hh];
                __half h0 = __float2half_rn(sv[0]);
                __half h1 = __float2half_rn(sv[1]);
                __half h2 = __float2half_rn(sv[2]);
                __half h3 = __float2half_rn(sv[3]);
                __half2 p01 = __halves2half2(h0, h1);
                __half2 p23 = __halves2half2(h2, h3);
                afh[2 * hh]     = *(uint32_t*)&p01;
                afh[2 * hh + 1] = *(uint32_t*)&p23;
                afl[2 * hh]     = pkh(sv[0] - __half2float(h0),
                                      sv[1] - __half2float(h1));
                afl[2 * hh + 1] = pkh(sv[2] - __half2float(h2),
                                      sv[3] - __half2float(h3));
            }

            #pragma unroll
            for (int nc = 0; nc < 4; nc++) {
                uint32_t off = (uint32_t)(((kt * 16 + v_row) * VSTR + nc * 16 + v_col) * 2);
                uint32_t vb[4];
                ldm4t(vb, pVf + off);
                mma16816(o[2 * nc],     afh, vb[0], vb[1]);
                mma16816(o[2 * nc],     afl, vb[0], vb[1]);
                mma16816(o[2 * nc + 1], afh, vb[2], vb[3]);
                mma16816(o[2 * nc + 1], afl, vb[2], vb[3]);
            }
        }

        __syncthreads();
        if (jb + 2 <= qb) issue(jb & 1, jb + 2);
    }

    float inv0 = 1.0f / l0, inv1 = 1.0f / l1;
    #pragma unroll
    for (int nt = 0; nt < 8; nt++) {
        int col = hcol + nt * 8 + (lane & 3) * 2;
        {
            float x = o[nt][0] * inv0, y = o[nt][1] * inv0;
            __half hx = __float2half_rn(x), hy = __float2half_rn(y);
            __half2 hp = __halves2half2(hx, hy);
            size_t d = ((size_t)myrow0 * D_MODEL + col) / 2;
            ((uint32_t*)ohi)[d] = *(uint32_t*)&hp;
            ((uint32_t*)olo)[d] = pkh(x - __half2float(hx), y - __half2float(hy));
        }
        {
            float x = o[nt][2] * inv1, y = o[nt][3] * inv1;
            __half hx = __float2half_rn(x), hy = __float2half_rn(y);
            __half2 hp = __halves2half2(hx, hy);
            size_t d = ((size_t)(myrow0 + 8) * D_MODEL + col) / 2;
            ((uint32_t*)ohi)[d] = *(uint32_t*)&hp;
            ((uint32_t*)olo)[d] = pkh(x - __half2float(hx), y - __half2float(hy));
        }
    }
}

// ---------------------------------------------------------------------------
extern "C" void kernel_launch(void* const* d_in, const int* in_sizes, int n_in,
                              void* d_out, int out_size)
{
    const float* x  = (const float*)d_in[0];
    const float* Wq = (const float*)d_in[1];
    const float* Wk = (const float*)d_in[2];
    const float* Wv = (const float*)d_in[3];
    const float* Wo = (const float*)d_in[4];

    float* qkv;
    __half *xhi, *xlo, *qhi, *qlo, *kf, *vf, *ohi, *olo, *wf, *wof;
    cudaGetSymbolAddress((void**)&qkv, g_qkv);
    cudaGetSymbolAddress((void**)&xhi, g_xhi);
    cudaGetSymbolAddress((void**)&xlo, g_xlo);
    cudaGetSymbolAddress((void**)&qhi, g_qhi);
    cudaGetSymbolAddress((void**)&qlo, g_qlo);
    cudaGetSymbolAddress((void**)&kf,  g_kf);
    cudaGetSymbolAddress((void**)&vf,  g_vf);
    cudaGetSymbolAddress((void**)&ohi, g_ohi);
    cudaGetSymbolAddress((void**)&olo, g_olo);
    cudaGetSymbolAddress((void**)&wf,  g_wf);
    cudaGetSymbolAddress((void**)&wof, g_wof);

    cudaFuncSetAttribute(gemm_fp16,
                         cudaFuncAttributeMaxDynamicSharedMemorySize, GSMEM);
    cudaFuncSetAttribute(flash_tc,
                         cudaFuncAttributeMaxDynamicSharedMemorySize, FSMEM2);

    const int NE4 = NSEQ * D_MODEL / 4;

    split_kernel<<<NE4 / 256, 256>>>(x, xhi, xlo);
    tconv4_kernel<<<dim3(D_MODEL / 32, D_MODEL / 32, 4), dim3(32, 8)>>>(
        Wq, Wk, Wv, Wo, wf, wof);

    gemm_fp16<<<dim3(D3 / 256, NSEQ / 128), 256, GSMEM>>>(
        xhi, xlo, wf, qkv, NSEQ, D3, D_MODEL);

    l2split_kernel<<<NSEQ * 48 / 8, 256>>>(qkv, qhi, qlo, kf, vf);

    flash_tc<<<dim3(NSEQ / 64, HEADS), 128, FSMEM2>>>(
        qhi, qlo, kf, vf, ohi, olo);

    gemm_fp16<<<dim3(D_MODEL / 256, NSEQ / 128), 256, GSMEM>>>(
        ohi, olo, wof, (float*)d_out, NSEQ, D_MODEL, D_MODEL);
}

// round 13
// speedup vs baseline: 1.6818x; 1.0368x over previous
#include <cuda_runtime.h>
#include <cuda_fp16.h>
#include <math.h>
#include <stdint.h>

#define D_MODEL 1024
#define D3      3072
#define NSEQ    4096
#define HEADS   16
#define DH      64

// Scratch (allocation-free rule: __device__ globals)
__device__ __half g_xhi[NSEQ * D_MODEL];
__device__ __half g_xlo[NSEQ * D_MODEL];
__device__ __half g_qhi[NSEQ * D_MODEL];
__device__ __half g_qlo[NSEQ * D_MODEL];
__device__ __half g_kf [NSEQ * D_MODEL];
__device__ __half g_vf [NSEQ * D_MODEL];
__device__ __half g_ohi[NSEQ * D_MODEL];
__device__ __half g_olo[NSEQ * D_MODEL];
__device__ __half g_wf [D3 * D_MODEL];              // Wqkv^T fp16 [N][K] concat
__device__ __half g_wof[D_MODEL * D_MODEL];         // Wo^T fp16

__device__ __forceinline__ uint32_t smem_u32(const void* p) {
    uint32_t a;
    asm("{ .reg .u64 t; cvta.to.shared.u64 t, %1; cvt.u32.u64 %0, t; }"
        : "=r"(a) : "l"(p));
    return a;
}

__device__ __forceinline__ void ldm4(uint32_t r[4], uint32_t addr) {
    asm volatile("ldmatrix.sync.aligned.m8n8.x4.shared.b16 {%0,%1,%2,%3}, [%4];"
                 : "=r"(r[0]), "=r"(r[1]), "=r"(r[2]), "=r"(r[3]) : "r"(addr));
}

__device__ __forceinline__ void ldm4t(uint32_t r[4], uint32_t addr) {
    asm volatile("ldmatrix.sync.aligned.m8n8.x4.trans.shared.b16 {%0,%1,%2,%3}, [%4];"
                 : "=r"(r[0]), "=r"(r[1]), "=r"(r[2]), "=r"(r[3]) : "r"(addr));
}

__device__ __forceinline__ void mma16816(float d[4], const uint32_t a[4],
                                         uint32_t b0, uint32_t b1) {
    asm volatile(
        "mma.sync.aligned.m16n8k16.row.col.f32.f16.f16.f32 "
        "{%0,%1,%2,%3}, {%4,%5,%6,%7}, {%8,%9}, {%0,%1,%2,%3};"
        : "+f"(d[0]), "+f"(d[1]), "+f"(d[2]), "+f"(d[3])
        : "r"(a[0]), "r"(a[1]), "r"(a[2]), "r"(a[3]), "r"(b0), "r"(b1));
}

__device__ __forceinline__ void cp16(uint32_t dst, const void* src) {
    asm volatile("cp.async.cg.shared.global [%0], [%1], 16;"
                 :: "r"(dst), "l"(src));
}

__device__ __forceinline__ uint32_t pkh(float x, float y) {
    __half2 h = __floats2half2_rn(x, y);
    return *(uint32_t*)&h;
}

// ---------------------------------------------------------------------------
// split: fp32 -> (hi, lo) fp16, same layout. 4 elements / thread.
// ---------------------------------------------------------------------------
__global__ void split_kernel(const float* __restrict__ in,
                             __half* __restrict__ hi, __half* __restrict__ lo)
{
    int i = blockIdx.x * blockDim.x + threadIdx.x;
    float4 v = ((const float4*)in)[i];
    __half h0 = __float2half_rn(v.x), h1 = __float2half_rn(v.y);
    __half h2 = __float2half_rn(v.z), h3 = __float2half_rn(v.w);
    float l0 = v.x - __half2float(h0), l1 = v.y - __half2float(h1);
    float l2 = v.z - __half2float(h2), l3 = v.w - __half2float(h3);
    __half2 hA = __halves2half2(h0, h1), hB = __halves2half2(h2, h3);
    ((uint2*)hi)[i] = make_uint2(*(uint32_t*)&hA, *(uint32_t*)&hB);
    ((uint2*)lo)[i] = make_uint2(pkh(l0, l1), pkh(l2, l3));
}

// ---------------------------------------------------------------------------
// fused transpose-convert of all 4 weights (z selects matrix) to single fp16.
// ---------------------------------------------------------------------------
__global__ void tconv4_kernel(const float* __restrict__ Wq,
                              const float* __restrict__ Wk,
                              const float* __restrict__ Wv,
                              const float* __restrict__ Wo,
                              __half* __restrict__ wf, __half* __restrict__ wof)
{
    __shared__ float tile[32][33];
    const int z = blockIdx.z;
    const float* W = (z == 0) ? Wq : (z == 1) ? Wk : (z == 2) ? Wv : Wo;
    __half* dh = (z == 3) ? wof : wf + (size_t)z * D_MODEL * D_MODEL;

    const int n0 = blockIdx.x * 32, k0 = blockIdx.y * 32;
    const int tx = threadIdx.x, ty = threadIdx.y;   // 32 x 8
    #pragma unroll
    for (int j = 0; j < 4; j++)
        tile[ty + 8 * j][tx] = W[(size_t)(k0 + ty + 8 * j) * D_MODEL + n0 + tx];
    __syncthreads();
    #pragma unroll
    for (int j = 0; j < 4; j++) {
        float v = tile[tx][ty + 8 * j];
        dh[(size_t)(n0 + ty + 8 * j) * D_MODEL + k0 + tx] = __float2half_rn(v);
    }
}

// ---------------------------------------------------------------------------
// Pipelined 2-pass fp16 GEMM.  C[M,N] = (Ahi+Alo)[M][K] @ Bf^T[N][K].
// CTA 128x256, BK=32, 8 warps (2x4, warp tile 64x64), 3-stage cp.async.
// fused=1: QKV epilogue — per-head l2norm of q,k (warp tile = one head) and
// direct fp16 stores (q split hi/lo, k/v single), no fp32 C.
// ---------------------------------------------------------------------------
#define ASTR 40
#define A_SZ (128 * ASTR * 2)                 // 10240 bytes per A matrix
#define B_SZ (256 * ASTR * 2)                 // 20480 bytes for Bf
#define STG_B (2 * A_SZ + B_SZ)               // 40960
#define GSMEM (3 * STG_B)                     // 122880

__global__ __launch_bounds__(256, 1) void gemm_fp16(
    const __half* __restrict__ Ahi, const __half* __restrict__ Alo,
    const __half* __restrict__ Bf,
    float* __restrict__ C,
    __half* __restrict__ qhi, __half* __restrict__ qlo,
    __half* __restrict__ kf, __half* __restrict__ vf,
    int M, int N, int K, int fused)
{
    extern __shared__ __align__(16) __half smg[];
    const uint32_t sb = smem_u32(smg);
    const int t = threadIdx.x;
    const int wid = t >> 5, lane = t & 31;
    const int row0 = blockIdx.y * 128, col0 = blockIdx.x * 256;
    const int wm = (wid >> 2) * 64;    // 0 / 64
    const int wn = (wid & 3) * 64;     // 0..192

    const int r_c = t >> 2, c_c = t & 3;   // cp.async coords

    float acc[4][8][4];
    #pragma unroll
    for (int i = 0; i < 4; i++)
        #pragma unroll
        for (int j = 0; j < 8; j++)
            #pragma unroll
            for (int q = 0; q < 4; q++) acc[i][j][q] = 0.f;

    auto issue = [&](int stage, int k0) {
        uint32_t s0 = sb + (uint32_t)(stage * STG_B);
        #pragma unroll
        for (int h = 0; h < 2; h++) {
            int r = r_c + h * 64;
            uint32_t o = (uint32_t)((r * ASTR + c_c * 8) * 2);
            const size_t g = (size_t)(row0 + r) * K + k0 + c_c * 8;
            cp16(s0 + o,        Ahi + g);
            cp16(s0 + A_SZ + o, Alo + g);
        }
        #pragma unroll
        for (int h = 0; h < 4; h++) {
            int r = r_c + h * 64;
            uint32_t o = (uint32_t)((r * ASTR + c_c * 8) * 2);
            const size_t g = (size_t)(col0 + r) * K + k0 + c_c * 8;
            cp16(s0 + 2 * A_SZ + o, Bf + g);
        }
        asm volatile("cp.async.commit_group;");
    };

    issue(0, 0);
    issue(1, 32);

    const int a_row = (lane & 7) + (lane & 8);
    const int a_col = (lane >> 4) << 3;
    const int b_row = (lane & 7) + ((lane & 16) >> 1);
    const int b_col = lane & 8;

    const int NIT = K >> 5;          // 32
    int stage = 0;
    for (int it = 0; it < NIT; it++) {
        asm volatile("cp.async.wait_group 1;");
        __syncthreads();

        const uint32_t s0 = sb + (uint32_t)(stage * STG_B);
        const uint32_t sAh = s0;
        const uint32_t sAl = s0 + A_SZ;
        const uint32_t sBf = s0 + 2 * A_SZ;

        #pragma unroll
        for (int ks = 0; ks < 2; ks++) {
            const int kb = ks * 16;
            uint32_t ah[4][4], al[4][4];
            #pragma unroll
            for (int mt = 0; mt < 4; mt++) {
                uint32_t off = (uint32_t)(((wm + mt * 16 + a_row) * ASTR + kb + a_col) * 2);
                ldm4(ah[mt], sAh + off);
                ldm4(al[mt], sAl + off);
            }
            #pragma unroll
            for (int p = 0; p < 4; p++) {
                uint32_t bf[4];
                uint32_t off = (uint32_t)(((wn + p * 16 + b_row) * ASTR + kb + b_col) * 2);
                ldm4(bf, sBf + off);
                #pragma unroll
                for (int mt = 0; mt < 4; mt++) {
                    #pragma unroll
                    for (int half = 0; half < 2; half++) {
                        int nt = p * 2 + half, si = half * 2;
                        mma16816(acc[mt][nt], ah[mt], bf[si], bf[si + 1]);
                        mma16816(acc[mt][nt], al[mt], bf[si], bf[si + 1]);
                    }
                }
            }
        }

        if (it + 2 < NIT) {
            int ns = stage + 2;
            if (ns >= 3) ns -= 3;
            issue(ns, (it + 2) * 32);
        }
        stage = (stage + 1 == 3) ? 0 : stage + 1;
    }

    if (!fused) {
        #pragma unroll
        for (int mt = 0; mt < 4; mt++)
            #pragma unroll
            for (int nt = 0; nt < 8; nt++) {
                int row = row0 + wm + mt * 16 + (lane >> 2);
                int col = col0 + wn + nt * 8 + (lane & 3) * 2;
                *(float2*)(C + (size_t)row * N + col) =
                    make_float2(acc[mt][nt][0], acc[mt][nt][1]);
                *(float2*)(C + (size_t)(row + 8) * N + col) =
                    make_float2(acc[mt][nt][2], acc[mt][nt][3]);
            }
        return;
    }

    // ---- fused QKV epilogue.  Warp tile = 64 cols = one head.
    const int gcol   = col0 + wn;           // multiple of 64
    const int region = gcol >> 10;          // 0=q, 1=k, 2=v
    const int dcol   = gcol & 1023;

    #pragma unroll
    for (int mt = 0; mt < 4; mt++) {
        float s0f = 1.f, s1f = 1.f;
        if (region < 2) {
            float ss0 = 0.f, ss1 = 0.f;
            #pragma unroll
            for (int nt = 0; nt < 8; nt++) {
                ss0 += acc[mt][nt][0] * acc[mt][nt][0]
                     + acc[mt][nt][1] * acc[mt][nt][1];
                ss1 += acc[mt][nt][2] * acc[mt][nt][2]
                     + acc[mt][nt][3] * acc[mt][nt][3];
            }
            ss0 += __shfl_xor_sync(0xffffffffu, ss0, 1);
            ss0 += __shfl_xor_sync(0xffffffffu, ss0, 2);
            ss1 += __shfl_xor_sync(0xffffffffu, ss1, 1);
            ss1 += __shfl_xor_sync(0xffffffffu, ss1, 2);
            s0f = 1.0f / fmaxf(sqrtf(ss0), 1e-12f);
            s1f = 1.0f / fmaxf(sqrtf(ss1), 1e-12f);
        }

        const int row = row0 + wm + mt * 16 + (lane >> 2);
        #pragma unroll
        for (int nt = 0; nt < 8; nt++) {
            int col = dcol + nt * 8 + (lane & 3) * 2;
            size_t d0 = ((size_t)row * D_MODEL + col) / 2;
            size_t d1 = ((size_t)(row + 8) * D_MODEL + col) / 2;
            float x0 = acc[mt][nt][0] * s0f, y0 = acc[mt][nt][1] * s0f;
            float x1 = acc[mt][nt][2] * s1f, y1 = acc[mt][nt][3] * s1f;
            if (region == 0) {
                __half hx0 = __float2half_rn(x0), hy0 = __float2half_rn(y0);
                __half hx1 = __float2half_rn(x1), hy1 = __float2half_rn(y1);
                __half2 p0 = __halves2half2(hx0, hy0);
                __half2 p1 = __halves2half2(hx1, hy1);
                ((uint32_t*)qhi)[d0] = *(uint32_t*)&p0;
                ((uint32_t*)qhi)[d1] = *(uint32_t*)&p1;
                ((uint32_t*)qlo)[d0] = pkh(x0 - __half2float(hx0),
                                           y0 - __half2float(hy0));
                ((uint32_t*)qlo)[d1] = pkh(x1 - __half2float(hx1),
                                           y1 - __half2float(hy1));
            } else {
                __half* dst = (region == 1) ? kf : vf;
                ((uint32_t*)dst)[d0] = pkh(x0, y0);
                ((uint32_t*)dst)[d1] = pkh(x1, y1);
            }
        }
    }
}

// ---------------------------------------------------------------------------
// Tensor-core flash attention (causal, scale=8), 2-pass fp16.
// BM=64 (4 warps x m16), BN=64, DH=64.  Q split (exact), K/V rounded once.
// ---------------------------------------------------------------------------
#define VSTR 72
#define MATB (64 * VSTR * 2)          // 9216 bytes per matrix
#define FSTGB (2 * MATB)              // Kf + Vf per stage
#define FSMEM2 (2 * FSTGB)            // 36864

__global__ __launch_bounds__(128) void flash_tc(
    const __half* __restrict__ qhi, const __half* __restrict__ qlo,
    const __half* __restrict__ kf, const __half* __restrict__ vf,
    __half* __restrict__ ohi, __half* __restrict__ olo)
{
    extern __shared__ __align__(16) __half smx[];
    const uint32_t sb = smem_u32(smx);
    const int qb = blockIdx.x, head = blockIdx.y;
    const int t = threadIdx.x, w = t >> 5, lane = t & 31;
    const int hcol = head * DH;

    const int lr = t >> 1, lh = (t & 1) * 32;

    auto ldmat = [&](uint32_t base, const __half* m, int seq0) {
        const size_t g = (size_t)(seq0 + lr) * D_MODEL + hcol + lh;
        uint32_t d = base + (uint32_t)((lr * VSTR + lh) * 2);
        #pragma unroll
        for (int q2 = 0; q2 < 4; q2++)
            cp16(d + q2 * 16, m + g + q2 * 8);
    };

    // ---- stage Q hi/lo through stage-0 slots, extract A-fragments
    ldmat(sb, qhi, qb * 64);
    ldmat(sb + MATB, qlo, qb * 64);
    asm volatile("cp.async.commit_group;");
    asm volatile("cp.async.wait_group 0;");
    __syncthreads();

    const int a_row = (lane & 7) + (lane & 8);
    const int a_col = (lane >> 4) << 3;
    uint32_t ah[4][4], al[4][4];
    #pragma unroll
    for (int kc = 0; kc < 4; kc++) {
        uint32_t off = (uint32_t)(((w * 16 + a_row) * VSTR + kc * 16 + a_col) * 2);
        ldm4(ah[kc], sb + off);
        ldm4(al[kc], sb + MATB + off);
    }
    __syncthreads();

    auto issue = [&](int stage, int jb) {
        uint32_t s0 = sb + (uint32_t)(stage * FSTGB);
        ldmat(s0,        kf, jb * 64);
        ldmat(s0 + MATB, vf, jb * 64);
        asm volatile("cp.async.commit_group;");
    };
    issue(0, 0);
    if (qb >= 1) issue(1, 1);

    float o[8][4];
    #pragma unroll
    for (int i = 0; i < 8; i++)
        #pragma unroll
        for (int j = 0; j < 4; j++) o[i][j] = 0.f;
    float m0 = -1e30f, m1 = -1e30f, l0 = 0.f, l1 = 0.f;

    const int b_row = (lane & 7) + ((lane & 16) >> 1);
    const int b_col = lane & 8;
    const int vg = lane >> 3;
    const int v_row = (vg & 1) * 8 + (lane & 7);
    const int v_col = (vg >> 1) * 8;
    const int myrow0 = qb * 64 + w * 16 + (lane >> 2);

    for (int jb = 0; jb <= qb; jb++) {
        if (jb < qb) asm volatile("cp.async.wait_group 1;");
        else         asm volatile("cp.async.wait_group 0;");
        __syncthreads();

        const uint32_t s0 = sb + (uint32_t)((jb & 1) * FSTGB);
        const uint32_t pKf = s0, pVf = s0 + MATB;

        float s[8][4];
        #pragma unroll
        for (int i = 0; i < 8; i++)
            #pragma unroll
            for (int j = 0; j < 4; j++) s[i][j] = 0.f;

        #pragma unroll
        for (int kc = 0; kc < 4; kc++) {
            uint32_t bh[4][4];
            #pragma unroll
            for (int p = 0; p < 4; p++) {
                uint32_t off = (uint32_t)(((p * 16 + b_row) * VSTR + kc * 16 + b_col) * 2);
                ldm4(bh[p], pKf + off);
            }
            #pragma unroll
            for (int nt = 0; nt < 8; nt++) {
                int p = nt >> 1, si = (nt & 1) * 2;
                mma16816(s[nt], ah[kc], bh[p][si], bh[p][si + 1]);
                mma16816(s[nt], al[kc], bh[p][si], bh[p][si + 1]);
            }
        }

        if (jb == qb) {
            #pragma unroll
            for (int nt = 0; nt < 8; nt++) {
                int colb = jb * 64 + nt * 8 + (lane & 3) * 2;
                #pragma unroll
                for (int c = 0; c < 4; c++) {
                    int col = colb + (c & 1);
                    int row = myrow0 + (c >> 1) * 8;
                    s[nt][c] = (col > row) ? -1e30f : s[nt][c] * 8.0f;
                }
            }
        } else {
            #pragma unroll
            for (int nt = 0; nt < 8; nt++)
                #pragma unroll
                for (int c = 0; c < 4; c++) s[nt][c] *= 8.0f;
        }

        float mx0 = -1e30f, mx1 = -1e30f;
        #pragma unroll
        for (int nt = 0; nt < 8; nt++) {
            mx0 = fmaxf(mx0, fmaxf(s[nt][0], s[nt][1]));
            mx1 = fmaxf(mx1, fmaxf(s[nt][2], s[nt][3]));
        }
        mx0 = fmaxf(mx0, __shfl_xor_sync(0xffffffffu, mx0, 1));
        mx0 = fmaxf(mx0, __shfl_xor_sync(0xffffffffu, mx0, 2));
        mx1 = fmaxf(mx1, __shfl_xor_sync(0xffffffffu, mx1, 1));
        mx1 = fmaxf(mx1, __shfl_xor_sync(0xffffffffu, mx1, 2));
        float mn0 = fmaxf(m0, mx0), mn1 = fmaxf(m1, mx1);
        float c0 = __expf(m0 - mn0), c1 = __expf(m1 - mn1);
        m0 = mn0; m1 = mn1;

        float rs0 = 0.f, rs1 = 0.f;
        #pragma unroll
        for (int nt = 0; nt < 8; nt++) {
            s[nt][0] = __expf(s[nt][0] - mn0);
            s[nt][1] = __expf(s[nt][1] - mn0);
            s[nt][2] = __expf(s[nt][2] - mn1);
            s[nt][3] = __expf(s[nt][3] - mn1);
            rs0 += s[nt][0] + s[nt][1];
            rs1 += s[nt][2] + s[nt][3];
        }
        rs0 += __shfl_xor_sync(0xffffffffu, rs0, 1);
        rs0 += __shfl_xor_sync(0xffffffffu, rs0, 2);
        rs1 += __shfl_xor_sync(0xffffffffu, rs1, 1);
        rs1 += __shfl_xor_sync(0xffffffffu, rs1, 2);
        l0 = l0 * c0 + rs0;
        l1 = l1 * c1 + rs1;
        #pragma unroll
        for (int nt = 0; nt < 8; nt++) {
            o[nt][0] *= c0; o[nt][1] *= c0;
            o[nt][2] *= c1; o[nt][3] *= c1;
        }

        // ---- O += P V (2 passes): P split into fp16 hi/lo in regs, V single
        #pragma unroll
        for (int kt = 0; kt < 4; kt++) {
            uint32_t afh[4], afl[4];
            #pragma unroll
            for (int hh = 0; hh < 2; hh++) {
                const float* sv = s[2 * kt + hh];
                __half h0 = __float2half_rn(sv[0]);
                __half h1 = __float2half_rn(sv[1]);
                __half h2 = __float2half_rn(sv[2]);
                __half h3 = __float2half_rn(sv[3]);
                __half2 p01 = __halves2half2(h0, h1);
                __half2 p23 = __halves2half2(h2, h3);
                afh[2 * hh]     = *(uint32_t*)&p01;
                afh[2 * hh + 1] = *(uint32_t*)&p23;
                afl[2 * hh]     = pkh(sv[0] - __half2float(h0),
                                      sv[1] - __half2float(h1));
                afl[2 * hh + 1] = pkh(sv[2] - __half2float(h2),
                                      sv[3] - __half2float(h3));
            }

            #pragma unroll
            for (int nc = 0; nc < 4; nc++) {
                uint32_t off = (uint32_t)(((kt * 16 + v_row) * VSTR + nc * 16 + v_col) * 2);
                uint32_t vb[4];
                ldm4t(vb, pVf + off);
                mma16816(o[2 * nc],     afh, vb[0], vb[1]);
                mma16816(o[2 * nc],     afl, vb[0], vb[1]);
                mma16816(o[2 * nc + 1], afh, vb[2], vb[3]);
                mma16816(o[2 * nc + 1], afl, vb[2], vb[3]);
            }
        }

        __syncthreads();
        if (jb + 2 <= qb) issue(jb & 1, jb + 2);
    }

    float inv0 = 1.0f / l0, inv1 = 1.0f / l1;
    #pragma unroll
    for (int nt = 0; nt < 8; nt++) {
        int col = hcol + nt * 8 + (lane & 3) * 2;
        {
            float x = o[nt][0] * inv0, y = o[nt][1] * inv0;
            __half hx = __float2half_rn(x), hy = __float2half_rn(y);
            __half2 hp = __halves2half2(hx, hy);
            size_t d = ((size_t)myrow0 * D_MODEL + col) / 2;
            ((uint32_t*)ohi)[d] = *(uint32_t*)&hp;
            ((uint32_t*)olo)[d] = pkh(x - __half2float(hx), y - __half2float(hy));
        }
        {
            float x = o[nt][2] * inv1, y = o[nt][3] * inv1;
            __half hx = __float2half_rn(x), hy = __float2half_rn(y);
            __half2 hp = __halves2half2(hx, hy);
            size_t d = ((size_t)(myrow0 + 8) * D_MODEL + col) / 2;
            ((uint32_t*)ohi)[d] = *(uint32_t*)&hp;
            ((uint32_t*)olo)[d] = pkh(x - __half2float(hx), y - __half2float(hy));
        }
    }
}

// ---------------------------------------------------------------------------
extern "C" void kernel_launch(void* const* d_in, const int* in_sizes, int n_in,
                              void* d_out, int out_size)
{
    const float* x  = (const float*)d_in[0];
    const float* Wq = (const float*)d_in[1];
    const float* Wk = (const float*)d_in[2];
    const float* Wv = (const float*)d_in[3];
    const float* Wo = (const float*)d_in[4];

    __half *xhi, *xlo, *qhi, *qlo, *kf, *vf, *ohi, *olo, *wf, *wof;
    cudaGetSymbolAddress((void**)&xhi, g_xhi);
    cudaGetSymbolAddress((void**)&xlo, g_xlo);
    cudaGetSymbolAddress((void**)&qhi, g_qhi);
    cudaGetSymbolAddress((void**)&qlo, g_qlo);
    cudaGetSymbolAddress((void**)&kf,  g_kf);
    cudaGetSymbolAddress((void**)&vf,  g_vf);
    cudaGetSymbolAddress((void**)&ohi, g_ohi);
    cudaGetSymbolAddress((void**)&olo, g_olo);
    cudaGetSymbolAddress((void**)&wf,  g_wf);
    cudaGetSymbolAddress((void**)&wof, g_wof);

    cudaFuncSetAttribute(gemm_fp16,
                         cudaFuncAttributeMaxDynamicSharedMemorySize, GSMEM);
    cudaFuncSetAttribute(flash_tc,
                         cudaFuncAttributeMaxDynamicSharedMemorySize, FSMEM2);

    const int NE4 = NSEQ * D_MODEL / 4;

    split_kernel<<<NE4 / 256, 256>>>(x, xhi, xlo);
    tconv4_kernel<<<dim3(D_MODEL / 32, D_MODEL / 32, 4), dim3(32, 8)>>>(
        Wq, Wk, Wv, Wo, wf, wof);

    // fused QKV GEMM + l2norm + fp16 split epilogue
    gemm_fp16<<<dim3(D3 / 256, NSEQ / 128), 256, GSMEM>>>(
        xhi, xlo, wf, nullptr, qhi, qlo, kf, vf, NSEQ, D3, D_MODEL, 1);

    flash_tc<<<dim3(NSEQ / 64, HEADS), 128, FSMEM2>>>(
        qhi, qlo, kf, vf, ohi, olo);

    gemm_fp16<<<dim3(D_MODEL / 256, NSEQ / 128), 256, GSMEM>>>(
        ohi, olo, wof, (float*)d_out, nullptr, nullptr, nullptr, nullptr,
        NSEQ, D_MODEL, D_MODEL, 0);
}

// round 14
// speedup vs baseline: 1.9736x; 1.1735x over previous
#include <cuda_runtime.h>
#include <cuda_fp16.h>
#include <math.h>
#include <stdint.h>

#define D_MODEL 1024
#define D3      3072
#define NSEQ    4096
#define HEADS   16
#define DH      64

// Scratch (allocation-free rule: __device__ globals)
__device__ __half g_xhi[NSEQ * D_MODEL];
__device__ __half g_xlo[NSEQ * D_MODEL];
__device__ __half g_qhi[NSEQ * D_MODEL];
__device__ __half g_qlo[NSEQ * D_MODEL];
__device__ __half g_kf [NSEQ * D_MODEL];
__device__ __half g_vf [NSEQ * D_MODEL];
__device__ __half g_of [NSEQ * D_MODEL];
__device__ __half g_wf [D3 * D_MODEL];              // Wqkv^T fp16 [N][K] concat
__device__ __half g_wof[D_MODEL * D_MODEL];         // Wo^T fp16

__device__ __forceinline__ uint32_t smem_u32(const void* p) {
    uint32_t a;
    asm("{ .reg .u64 t; cvta.to.shared.u64 t, %1; cvt.u32.u64 %0, t; }"
        : "=r"(a) : "l"(p));
    return a;
}

__device__ __forceinline__ void ldm4(uint32_t r[4], uint32_t addr) {
    asm volatile("ldmatrix.sync.aligned.m8n8.x4.shared.b16 {%0,%1,%2,%3}, [%4];"
                 : "=r"(r[0]), "=r"(r[1]), "=r"(r[2]), "=r"(r[3]) : "r"(addr));
}

__device__ __forceinline__ void ldm4t(uint32_t r[4], uint32_t addr) {
    asm volatile("ldmatrix.sync.aligned.m8n8.x4.trans.shared.b16 {%0,%1,%2,%3}, [%4];"
                 : "=r"(r[0]), "=r"(r[1]), "=r"(r[2]), "=r"(r[3]) : "r"(addr));
}

__device__ __forceinline__ void mma16816(float d[4], const uint32_t a[4],
                                         uint32_t b0, uint32_t b1) {
    asm volatile(
        "mma.sync.aligned.m16n8k16.row.col.f32.f16.f16.f32 "
        "{%0,%1,%2,%3}, {%4,%5,%6,%7}, {%8,%9}, {%0,%1,%2,%3};"
        : "+f"(d[0]), "+f"(d[1]), "+f"(d[2]), "+f"(d[3])
        : "r"(a[0]), "r"(a[1]), "r"(a[2]), "r"(a[3]), "r"(b0), "r"(b1));
}

__device__ __forceinline__ void cp16(uint32_t dst, const void* src) {
    asm volatile("cp.async.cg.shared.global [%0], [%1], 16;"
                 :: "r"(dst), "l"(src));
}

__device__ __forceinline__ uint32_t pkh(float x, float y) {
    __half2 h = __floats2half2_rn(x, y);
    return *(uint32_t*)&h;
}

// ---------------------------------------------------------------------------
// split: fp32 -> (hi, lo) fp16, same layout. 4 elements / thread.
// ---------------------------------------------------------------------------
__global__ void split_kernel(const float* __restrict__ in,
                             __half* __restrict__ hi, __half* __restrict__ lo)
{
    int i = blockIdx.x * blockDim.x + threadIdx.x;
    float4 v = ((const float4*)in)[i];
    __half h0 = __float2half_rn(v.x), h1 = __float2half_rn(v.y);
    __half h2 = __float2half_rn(v.z), h3 = __float2half_rn(v.w);
    float l0 = v.x - __half2float(h0), l1 = v.y - __half2float(h1);
    float l2 = v.z - __half2float(h2), l3 = v.w - __half2float(h3);
    __half2 hA = __halves2half2(h0, h1), hB = __halves2half2(h2, h3);
    ((uint2*)hi)[i] = make_uint2(*(uint32_t*)&hA, *(uint32_t*)&hB);
    ((uint2*)lo)[i] = make_uint2(pkh(l0, l1), pkh(l2, l3));
}

// ---------------------------------------------------------------------------
// fused transpose-convert of all 4 weights (z selects matrix) to single fp16.
// ---------------------------------------------------------------------------
__global__ void tconv4_kernel(const float* __restrict__ Wq,
                              const float* __restrict__ Wk,
                              const float* __restrict__ Wv,
                              const float* __restrict__ Wo,
                              __half* __restrict__ wf, __half* __restrict__ wof)
{
    __shared__ float tile[32][33];
    const int z = blockIdx.z;
    const float* W = (z == 0) ? Wq : (z == 1) ? Wk : (z == 2) ? Wv : Wo;
    __half* dh = (z == 3) ? wof : wf + (size_t)z * D_MODEL * D_MODEL;

    const int n0 = blockIdx.x * 32, k0 = blockIdx.y * 32;
    const int tx = threadIdx.x, ty = threadIdx.y;   // 32 x 8
    #pragma unroll
    for (int j = 0; j < 4; j++)
        tile[ty + 8 * j][tx] = W[(size_t)(k0 + ty + 8 * j) * D_MODEL + n0 + tx];
    __syncthreads();
    #pragma unroll
    for (int j = 0; j < 4; j++) {
        float v = tile[tx][ty + 8 * j];
        dh[(size_t)(n0 + ty + 8 * j) * D_MODEL + k0 + tx] = __float2half_rn(v);
    }
}

// ---------------------------------------------------------------------------
// Pipelined fp16 GEMM (NPASS = 1 or 2).  C = (Ahi[+Alo]) @ Bf^T.
// CTA 128x256, BK=32, 8 warps (2x4, warp tile 64x64), 3-stage cp.async.
// fused=1: QKV epilogue — per-head l2norm of q,k and direct fp16 stores.
// ---------------------------------------------------------------------------
#define ASTR 40
#define A_SZ (128 * ASTR * 2)                 // 10240 bytes per A matrix
#define B_SZ (256 * ASTR * 2)                 // 20480 bytes for Bf
#define STG_B (2 * A_SZ + B_SZ)               // 40960
#define GSMEM (3 * STG_B)                     // 122880

template <int NPASS>
__global__ __launch_bounds__(256, 1) void gemm_fp16(
    const __half* __restrict__ Ahi, const __half* __restrict__ Alo,
    const __half* __restrict__ Bf,
    float* __restrict__ C,
    __half* __restrict__ qhi, __half* __restrict__ qlo,
    __half* __restrict__ kf, __half* __restrict__ vf,
    int M, int N, int K, int fused)
{
    extern __shared__ __align__(16) __half smg[];
    const uint32_t sb = smem_u32(smg);
    const int t = threadIdx.x;
    const int wid = t >> 5, lane = t & 31;
    const int row0 = blockIdx.y * 128, col0 = blockIdx.x * 256;
    const int wm = (wid >> 2) * 64;    // 0 / 64
    const int wn = (wid & 3) * 64;     // 0..192

    const int r_c = t >> 2, c_c = t & 3;   // cp.async coords

    float acc[4][8][4];
    #pragma unroll
    for (int i = 0; i < 4; i++)
        #pragma unroll
        for (int j = 0; j < 8; j++)
            #pragma unroll
            for (int q = 0; q < 4; q++) acc[i][j][q] = 0.f;

    auto issue = [&](int stage, int k0) {
        uint32_t s0 = sb + (uint32_t)(stage * STG_B);
        #pragma unroll
        for (int h = 0; h < 2; h++) {
            int r = r_c + h * 64;
            uint32_t o = (uint32_t)((r * ASTR + c_c * 8) * 2);
            const size_t g = (size_t)(row0 + r) * K + k0 + c_c * 8;
            cp16(s0 + o, Ahi + g);
            if (NPASS == 2) cp16(s0 + A_SZ + o, Alo + g);
        }
        #pragma unroll
        for (int h = 0; h < 4; h++) {
            int r = r_c + h * 64;
            uint32_t o = (uint32_t)((r * ASTR + c_c * 8) * 2);
            const size_t g = (size_t)(col0 + r) * K + k0 + c_c * 8;
            cp16(s0 + 2 * A_SZ + o, Bf + g);
        }
        asm volatile("cp.async.commit_group;");
    };

    issue(0, 0);
    issue(1, 32);

    const int a_row = (lane & 7) + (lane & 8);
    const int a_col = (lane >> 4) << 3;
    const int b_row = (lane & 7) + ((lane & 16) >> 1);
    const int b_col = lane & 8;

    const int NIT = K >> 5;          // 32
    int stage = 0;
    for (int it = 0; it < NIT; it++) {
        asm volatile("cp.async.wait_group 1;");
        __syncthreads();

        const uint32_t s0 = sb + (uint32_t)(stage * STG_B);
        const uint32_t sAh = s0;
        const uint32_t sAl = s0 + A_SZ;
        const uint32_t sBf = s0 + 2 * A_SZ;

        #pragma unroll
        for (int ks = 0; ks < 2; ks++) {
            const int kb = ks * 16;
            uint32_t ah[4][4], al[4][4];
            #pragma unroll
            for (int mt = 0; mt < 4; mt++) {
                uint32_t off = (uint32_t)(((wm + mt * 16 + a_row) * ASTR + kb + a_col) * 2);
                ldm4(ah[mt], sAh + off);
                if (NPASS == 2) ldm4(al[mt], sAl + off);
            }
            #pragma unroll
            for (int p = 0; p < 4; p++) {
                uint32_t bf[4];
                uint32_t off = (uint32_t)(((wn + p * 16 + b_row) * ASTR + kb + b_col) * 2);
                ldm4(bf, sBf + off);
                #pragma unroll
                for (int mt = 0; mt < 4; mt++) {
                    #pragma unroll
                    for (int half = 0; half < 2; half++) {
                        int nt = p * 2 + half, si = half * 2;
                        mma16816(acc[mt][nt], ah[mt], bf[si], bf[si + 1]);
                        if (NPASS == 2)
                            mma16816(acc[mt][nt], al[mt], bf[si], bf[si + 1]);
                    }
                }
            }
        }

        if (it + 2 < NIT) {
            int ns = stage + 2;
            if (ns >= 3) ns -= 3;
            issue(ns, (it + 2) * 32);
        }
        stage = (stage + 1 == 3) ? 0 : stage + 1;
    }

    if (!fused) {
        #pragma unroll
        for (int mt = 0; mt < 4; mt++)
            #pragma unroll
            for (int nt = 0; nt < 8; nt++) {
                int row = row0 + wm + mt * 16 + (lane >> 2);
                int col = col0 + wn + nt * 8 + (lane & 3) * 2;
                *(float2*)(C + (size_t)row * N + col) =
                    make_float2(acc[mt][nt][0], acc[mt][nt][1]);
                *(float2*)(C + (size_t)(row + 8) * N + col) =
                    make_float2(acc[mt][nt][2], acc[mt][nt][3]);
            }
        return;
    }

    // ---- fused QKV epilogue.  Warp tile = 64 cols = one head.
    const int gcol   = col0 + wn;           // multiple of 64
    const int region = gcol >> 10;          // 0=q, 1=k, 2=v
    const int dcol   = gcol & 1023;

    #pragma unroll
    for (int mt = 0; mt < 4; mt++) {
        float s0f = 1.f, s1f = 1.f;
        if (region < 2) {
            float ss0 = 0.f, ss1 = 0.f;
            #pragma unroll
            for (int nt = 0; nt < 8; nt++) {
                ss0 += acc[mt][nt][0] * acc[mt][nt][0]
                     + acc[mt][nt][1] * acc[mt][nt][1];
                ss1 += acc[mt][nt][2] * acc[mt][nt][2]
                     + acc[mt][nt][3] * acc[mt][nt][3];
            }
            ss0 += __shfl_xor_sync(0xffffffffu, ss0, 1);
            ss0 += __shfl_xor_sync(0xffffffffu, ss0, 2);
            ss1 += __shfl_xor_sync(0xffffffffu, ss1, 1);
            ss1 += __shfl_xor_sync(0xffffffffu, ss1, 2);
            s0f = 1.0f / fmaxf(sqrtf(ss0), 1e-12f);
            s1f = 1.0f / fmaxf(sqrtf(ss1), 1e-12f);
        }

        const int row = row0 + wm + mt * 16 + (lane >> 2);
        #pragma unroll
        for (int nt = 0; nt < 8; nt++) {
            int col = dcol + nt * 8 + (lane & 3) * 2;
            size_t d0 = ((size_t)row * D_MODEL + col) / 2;
            size_t d1 = ((size_t)(row + 8) * D_MODEL + col) / 2;
            float x0 = acc[mt][nt][0] * s0f, y0 = acc[mt][nt][1] * s0f;
            float x1 = acc[mt][nt][2] * s1f, y1 = acc[mt][nt][3] * s1f;
            if (region == 0) {
                __half hx0 = __float2half_rn(x0), hy0 = __float2half_rn(y0);
                __half hx1 = __float2half_rn(x1), hy1 = __float2half_rn(y1);
                __half2 p0 = __halves2half2(hx0, hy0);
                __half2 p1 = __halves2half2(hx1, hy1);
                ((uint32_t*)qhi)[d0] = *(uint32_t*)&p0;
                ((uint32_t*)qhi)[d1] = *(uint32_t*)&p1;
                ((uint32_t*)qlo)[d0] = pkh(x0 - __half2float(hx0),
                                           y0 - __half2float(hy0));
                ((uint32_t*)qlo)[d1] = pkh(x1 - __half2float(hx1),
                                           y1 - __half2float(hy1));
            } else {
                __half* dst = (region == 1) ? kf : vf;
                ((uint32_t*)dst)[d0] = pkh(x0, y0);
                ((uint32_t*)dst)[d1] = pkh(x1, y1);
            }
        }
    }
}

// ---------------------------------------------------------------------------
// Tensor-core flash attention (causal, scale=8).
// QK 2-pass (q split, k rounded); PV 1-pass (P rounded, V rounded).
// BM=64 (4 warps x m16), BN=64, DH=64, double-buffered K/V.
// ---------------------------------------------------------------------------
#define VSTR 72
#define MATB (64 * VSTR * 2)          // 9216 bytes per matrix
#define FSTGB (2 * MATB)              // Kf + Vf per stage
#define FSMEM2 (2 * FSTGB)            // 36864

__global__ __launch_bounds__(128, 4) void flash_tc(
    const __half* __restrict__ qhi, const __half* __restrict__ qlo,
    const __half* __restrict__ kf, const __half* __restrict__ vf,
    __half* __restrict__ of)
{
    extern __shared__ __align__(16) __half smx[];
    const uint32_t sb = smem_u32(smx);
    const int qb = blockIdx.x, head = blockIdx.y;
    const int t = threadIdx.x, w = t >> 5, lane = t & 31;
    const int hcol = head * DH;

    const int lr = t >> 1, lh = (t & 1) * 32;

    auto ldmat = [&](uint32_t base, const __half* m, int seq0) {
        const size_t g = (size_t)(seq0 + lr) * D_MODEL + hcol + lh;
        uint32_t d = base + (uint32_t)((lr * VSTR + lh) * 2);
        #pragma unroll
        for (int q2 = 0; q2 < 4; q2++)
            cp16(d + q2 * 16, m + g + q2 * 8);
    };

    // ---- stage Q hi/lo through stage-0 slots, extract A-fragments
    ldmat(sb, qhi, qb * 64);
    ldmat(sb + MATB, qlo, qb * 64);
    asm volatile("cp.async.commit_group;");
    asm volatile("cp.async.wait_group 0;");
    __syncthreads();

    const int a_row = (lane & 7) + (lane & 8);
    const int a_col = (lane >> 4) << 3;
    uint32_t ah[4][4], al[4][4];
    #pragma unroll
    for (int kc = 0; kc < 4; kc++) {
        uint32_t off = (uint32_t)(((w * 16 + a_row) * VSTR + kc * 16 + a_col) * 2);
        ldm4(ah[kc], sb + off);
        ldm4(al[kc], sb + MATB + off);
    }
    __syncthreads();

    auto issue = [&](int stage, int jb) {
        uint32_t s0 = sb + (uint32_t)(stage * FSTGB);
        ldmat(s0,        kf, jb * 64);
        ldmat(s0 + MATB, vf, jb * 64);
        asm volatile("cp.async.commit_group;");
    };
    issue(0, 0);
    if (qb >= 1) issue(1, 1);

    float o[8][4];
    #pragma unroll
    for (int i = 0; i < 8; i++)
        #pragma unroll
        for (int j = 0; j < 4; j++) o[i][j] = 0.f;
    float m0 = -1e30f, m1 = -1e30f, l0 = 0.f, l1 = 0.f;

    const int b_row = (lane & 7) + ((lane & 16) >> 1);
    const int b_col = lane & 8;
    const int vg = lane >> 3;
    const int v_row = (vg & 1) * 8 + (lane & 7);
    const int v_col = (vg >> 1) * 8;
    const int myrow0 = qb * 64 + w * 16 + (lane >> 2);

    for (int jb = 0; jb <= qb; jb++) {
        if (jb < qb) asm volatile("cp.async.wait_group 1;");
        else         asm volatile("cp.async.wait_group 0;");
        __syncthreads();

        const uint32_t s0 = sb + (uint32_t)((jb & 1) * FSTGB);
        const uint32_t pKf = s0, pVf = s0 + MATB;

        float s[8][4];
        #pragma unroll
        for (int i = 0; i < 8; i++)
            #pragma unroll
            for (int j = 0; j < 4; j++) s[i][j] = 0.f;

        #pragma unroll
        for (int kc = 0; kc < 4; kc++) {
            uint32_t bh[4][4];
            #pragma unroll
            for (int p = 0; p < 4; p++) {
                uint32_t off = (uint32_t)(((p * 16 + b_row) * VSTR + kc * 16 + b_col) * 2);
                ldm4(bh[p], pKf + off);
            }
            #pragma unroll
            for (int nt = 0; nt < 8; nt++) {
                int p = nt >> 1, si = (nt & 1) * 2;
                mma16816(s[nt], ah[kc], bh[p][si], bh[p][si + 1]);
                mma16816(s[nt], al[kc], bh[p][si], bh[p][si + 1]);
            }
        }

        if (jb == qb) {
            #pragma unroll
            for (int nt = 0; nt < 8; nt++) {
                int colb = jb * 64 + nt * 8 + (lane & 3) * 2;
                #pragma unroll
                for (int c = 0; c < 4; c++) {
                    int col = colb + (c & 1);
                    int row = myrow0 + (c >> 1) * 8;
                    s[nt][c] = (col > row) ? -1e30f : s[nt][c] * 8.0f;
                }
            }
        } else {
            #pragma unroll
            for (int nt = 0; nt < 8; nt++)
                #pragma unroll
                for (int c = 0; c < 4; c++) s[nt][c] *= 8.0f;
        }

        float mx0 = -1e30f, mx1 = -1e30f;
        #pragma unroll
        for (int nt = 0; nt < 8; nt++) {
            mx0 = fmaxf(mx0, fmaxf(s[nt][0], s[nt][1]));
            mx1 = fmaxf(mx1, fmaxf(s[nt][2], s[nt][3]));
        }
        mx0 = fmaxf(mx0, __shfl_xor_sync(0xffffffffu, mx0, 1));
        mx0 = fmaxf(mx0, __shfl_xor_sync(0xffffffffu, mx0, 2));
        mx1 = fmaxf(mx1, __shfl_xor_sync(0xffffffffu, mx1, 1));
        mx1 = fmaxf(mx1, __shfl_xor_sync(0xffffffffu, mx1, 2));
        float mn0 = fmaxf(m0, mx0), mn1 = fmaxf(m1, mx1);
        float c0 = __expf(m0 - mn0), c1 = __expf(m1 - mn1);
        m0 = mn0; m1 = mn1;

        float rs0 = 0.f, rs1 = 0.f;
        #pragma unroll
        for (int nt = 0; nt < 8; nt++) {
            s[nt][0] = __expf(s[nt][0] - mn0);
            s[nt][1] = __expf(s[nt][1] - mn0);
            s[nt][2] = __expf(s[nt][2] - mn1);
            s[nt][3] = __expf(s[nt][3] - mn1);
            rs0 += s[nt][0] + s[nt][1];
            rs1 += s[nt][2] + s[nt][3];
        }
        rs0 += __shfl_xor_sync(0xffffffffu, rs0, 1);
        rs0 += __shfl_xor_sync(0xffffffffu, rs0, 2);
        rs1 += __shfl_xor_sync(0xffffffffu, rs1, 1);
        rs1 += __shfl_xor_sync(0xffffffffu, rs1, 2);
        l0 = l0 * c0 + rs0;
        l1 = l1 * c1 + rs1;
        #pragma unroll
        for (int nt = 0; nt < 8; nt++) {
            o[nt][0] *= c0; o[nt][1] *= c0;
            o[nt][2] *= c1; o[nt][3] *= c1;
        }

        // ---- O += P V (1 pass): P rounded to fp16 in regs, V single fp16
        #pragma unroll
        for (int kt = 0; kt < 4; kt++) {
            uint32_t afh[4];
            #pragma unroll
            for (int hh = 0; hh < 2; hh++) {
                const float* sv = s[2 * kt + hh];
                afh[2 * hh]     = pkh(sv[0], sv[1]);
                afh[2 * hh + 1] = pkh(sv[2], sv[3]);
            }

            #pragma unroll
            for (int nc = 0; nc < 4; nc++) {
                uint32_t off = (uint32_t)(((kt * 16 + v_row) * VSTR + nc * 16 + v_col) * 2);
                uint32_t vb[4];
                ldm4t(vb, pVf + off);
                mma16816(o[2 * nc],     afh, vb[0], vb[1]);
                mma16816(o[2 * nc + 1], afh, vb[2], vb[3]);
            }
        }

        __syncthreads();
        if (jb + 2 <= qb) issue(jb & 1, jb + 2);
    }

    float inv0 = 1.0f / l0, inv1 = 1.0f / l1;
    #pragma unroll
    for (int nt = 0; nt < 8; nt++) {
        int col = hcol + nt * 8 + (lane & 3) * 2;
        {
            float x = o[nt][0] * inv0, y = o[nt][1] * inv0;
            size_t d = ((size_t)myrow0 * D_MODEL + col) / 2;
            ((uint32_t*)of)[d] = pkh(x, y);
        }
        {
            float x = o[nt][2] * inv1, y = o[nt][3] * inv1;
            size_t d = ((size_t)(myrow0 + 8) * D_MODEL + col) / 2;
            ((uint32_t*)of)[d] = pkh(x, y);
        }
    }
}

// ---------------------------------------------------------------------------
extern "C" void kernel_launch(void* const* d_in, const int* in_sizes, int n_in,
                              void* d_out, int out_size)
{
    const float* x  = (const float*)d_in[0];
    const float* Wq = (const float*)d_in[1];
    const float* Wk = (const float*)d_in[2];
    const float* Wv = (const float*)d_in[3];
    const float* Wo = (const float*)d_in[4];

    __half *xhi, *xlo, *qhi, *qlo, *kf, *vf, *of, *wf, *wof;
    cudaGetSymbolAddress((void**)&xhi, g_xhi);
    cudaGetSymbolAddress((void**)&xlo, g_xlo);
    cudaGetSymbolAddress((void**)&qhi, g_qhi);
    cudaGetSymbolAddress((void**)&qlo, g_qlo);
    cudaGetSymbolAddress((void**)&kf,  g_kf);
    cudaGetSymbolAddress((void**)&vf,  g_vf);
    cudaGetSymbolAddress((void**)&of,  g_of);
    cudaGetSymbolAddress((void**)&wf,  g_wf);
    cudaGetSymbolAddress((void**)&wof, g_wof);

    cudaFuncSetAttribute(gemm_fp16<2>,
                         cudaFuncAttributeMaxDynamicSharedMemorySize, GSMEM);
    cudaFuncSetAttribute(gemm_fp16<1>,
                         cudaFuncAttributeMaxDynamicSharedMemorySize, GSMEM);
    cudaFuncSetAttribute(flash_tc,
                         cudaFuncAttributeMaxDynamicSharedMemorySize, FSMEM2);

    const int NE4 = NSEQ * D_MODEL / 4;

    split_kernel<<<NE4 / 256, 256>>>(x, xhi, xlo);
    tconv4_kernel<<<dim3(D_MODEL / 32, D_MODEL / 32, 4), dim3(32, 8)>>>(
        Wq, Wk, Wv, Wo, wf, wof);

    // fused QKV GEMM (2-pass) + l2norm + fp16 epilogue
    gemm_fp16<2><<<dim3(D3 / 256, NSEQ / 128), 256, GSMEM>>>(
        xhi, xlo, wf, nullptr, qhi, qlo, kf, vf, NSEQ, D3, D_MODEL, 1);

    flash_tc<<<dim3(NSEQ / 64, HEADS), 128, FSMEM2>>>(
        qhi, qlo, kf, vf, of);

    // out-proj (1-pass: o rounded once)
    gemm_fp16<1><<<dim3(D_MODEL / 256, NSEQ / 128), 256, GSMEM>>>(
        of, nullptr, wof, (float*)d_out, nullptr, nullptr, nullptr, nullptr,
        NSEQ, D_MODEL, D_MODEL, 0);
}

// round 16
// speedup vs baseline: 2.6156x; 1.3253x over previous
#include <cuda_runtime.h>
#include <cuda_fp16.h>
#include <math.h>
#include <stdint.h>

#define D_MODEL 1024
#define D3      3072
#define NSEQ    4096
#define HEADS   16
#define DH      64

// Scratch (allocation-free rule: __device__ globals)
__device__ __half g_xf [NSEQ * D_MODEL];
__device__ __half g_qf [NSEQ * D_MODEL];
__device__ __half g_kf [NSEQ * D_MODEL];
__device__ __half g_vf [NSEQ * D_MODEL];
__device__ __half g_of [NSEQ * D_MODEL];
__device__ __half g_wf [D3 * D_MODEL];              // Wqkv^T fp16 [N][K] concat
__device__ __half g_wof[D_MODEL * D_MODEL];         // Wo^T fp16

__device__ __forceinline__ uint32_t smem_u32(const void* p) {
    uint32_t a;
    asm("{ .reg .u64 t; cvta.to.shared.u64 t, %1; cvt.u32.u64 %0, t; }"
        : "=r"(a) : "l"(p));
    return a;
}

__device__ __forceinline__ void ldm4(uint32_t r[4], uint32_t addr) {
    asm volatile("ldmatrix.sync.aligned.m8n8.x4.shared.b16 {%0,%1,%2,%3}, [%4];"
                 : "=r"(r[0]), "=r"(r[1]), "=r"(r[2]), "=r"(r[3]) : "r"(addr));
}

__device__ __forceinline__ void ldm4t(uint32_t r[4], uint32_t addr) {
    asm volatile("ldmatrix.sync.aligned.m8n8.x4.trans.shared.b16 {%0,%1,%2,%3}, [%4];"
                 : "=r"(r[0]), "=r"(r[1]), "=r"(r[2]), "=r"(r[3]) : "r"(addr));
}

__device__ __forceinline__ void mma16816(float d[4], const uint32_t a[4],
                                         uint32_t b0, uint32_t b1) {
    asm volatile(
        "mma.sync.aligned.m16n8k16.row.col.f32.f16.f16.f32 "
        "{%0,%1,%2,%3}, {%4,%5,%6,%7}, {%8,%9}, {%0,%1,%2,%3};"
        : "+f"(d[0]), "+f"(d[1]), "+f"(d[2]), "+f"(d[3])
        : "r"(a[0]), "r"(a[1]), "r"(a[2]), "r"(a[3]), "r"(b0), "r"(b1));
}

__device__ __forceinline__ void cp16(uint32_t dst, const void* src) {
    asm volatile("cp.async.cg.shared.global [%0], [%1], 16;"
                 :: "r"(dst), "l"(src));
}

__device__ __forceinline__ uint32_t pkh(float x, float y) {
    __half2 h = __floats2half2_rn(x, y);
    return *(uint32_t*)&h;
}

// ---------------------------------------------------------------------------
// convert: fp32 -> fp16, 4 elements / thread.
// ---------------------------------------------------------------------------
__global__ void conv_kernel(const float* __restrict__ in,
                            __half* __restrict__ out)
{
    int i = blockIdx.x * blockDim.x + threadIdx.x;
    float4 v = ((const float4*)in)[i];
    ((uint2*)out)[i] = make_uint2(pkh(v.x, v.y), pkh(v.z, v.w));
}

// ---------------------------------------------------------------------------
// fused transpose-convert of all 4 weights (z selects matrix) to fp16.
// ---------------------------------------------------------------------------
__global__ void tconv4_kernel(const float* __restrict__ Wq,
                              const float* __restrict__ Wk,
                              const float* __restrict__ Wv,
                              const float* __restrict__ Wo,
                              __half* __restrict__ wf, __half* __restrict__ wof)
{
    __shared__ float tile[32][33];
    const int z = blockIdx.z;
    const float* W = (z == 0) ? Wq : (z == 1) ? Wk : (z == 2) ? Wv : Wo;
    __half* dh = (z == 3) ? wof : wf + (size_t)z * D_MODEL * D_MODEL;

    const int n0 = blockIdx.x * 32, k0 = blockIdx.y * 32;
    const int tx = threadIdx.x, ty = threadIdx.y;   // 32 x 8
    #pragma unroll
    for (int j = 0; j < 4; j++)
        tile[ty + 8 * j][tx] = W[(size_t)(k0 + ty + 8 * j) * D_MODEL + n0 + tx];
    __syncthreads();
    #pragma unroll
    for (int j = 0; j < 4; j++) {
        float v = tile[tx][ty + 8 * j];
        dh[(size_t)(n0 + ty + 8 * j) * D_MODEL + k0 + tx] = __float2half_rn(v);
    }
}

// ---------------------------------------------------------------------------
// Pipelined 1-pass fp16 GEMM.  C = Af @ Bf^T.
// CTA 128x256, BK=32, 8 warps (2x4, warp tile 64x64), 3-stage cp.async.
// fused=1: QKV epilogue — per-head l2norm of q,k and direct fp16 stores.
// ---------------------------------------------------------------------------
#define ASTR 40
#define A_SZ (128 * ASTR * 2)                 // 10240 bytes for Af
#define B_SZ (256 * ASTR * 2)                 // 20480 bytes for Bf
#define STG_B (A_SZ + B_SZ)                   // 30720
#define GSMEM (3 * STG_B)                     // 92160

__global__ __launch_bounds__(256, 1) void gemm_fp16(
    const __half* __restrict__ Af, const __half* __restrict__ Bf,
    float* __restrict__ C,
    __half* __restrict__ qf, __half* __restrict__ kf, __half* __restrict__ vf,
    int M, int N, int K, int fused)
{
    extern __shared__ __align__(16) __half smg[];
    const uint32_t sb = smem_u32(smg);
    const int t = threadIdx.x;
    const int wid = t >> 5, lane = t & 31;
    const int row0 = blockIdx.y * 128, col0 = blockIdx.x * 256;
    const int wm = (wid >> 2) * 64;    // 0 / 64
    const int wn = (wid & 3) * 64;     // 0..192

    const int r_c = t >> 2, c_c = t & 3;   // cp.async coords

    float acc[4][8][4];
    #pragma unroll
    for (int i = 0; i < 4; i++)
        #pragma unroll
        for (int j = 0; j < 8; j++)
            #pragma unroll
            for (int q = 0; q < 4; q++) acc[i][j][q] = 0.f;

    auto issue = [&](int stage, int k0) {
        uint32_t s0 = sb + (uint32_t)(stage * STG_B);
        #pragma unroll
        for (int h = 0; h < 2; h++) {
            int r = r_c + h * 64;
            uint32_t o = (uint32_t)((r * ASTR + c_c * 8) * 2);
            cp16(s0 + o, Af + (size_t)(row0 + r) * K + k0 + c_c * 8);
        }
        #pragma unroll
        for (int h = 0; h < 4; h++) {
            int r = r_c + h * 64;
            uint32_t o = (uint32_t)((r * ASTR + c_c * 8) * 2);
            cp16(s0 + A_SZ + o, Bf + (size_t)(col0 + r) * K + k0 + c_c * 8);
        }
        asm volatile("cp.async.commit_group;");
    };

    issue(0, 0);
    issue(1, 32);

    const int a_row = (lane & 7) + (lane & 8);
    const int a_col = (lane >> 4) << 3;
    const int b_row = (lane & 7) + ((lane & 16) >> 1);
    const int b_col = lane & 8;

    const int NIT = K >> 5;          // 32
    int stage = 0;
    for (int it = 0; it < NIT; it++) {
        asm volatile("cp.async.wait_group 1;");
        __syncthreads();

        const uint32_t s0 = sb + (uint32_t)(stage * STG_B);
        const uint32_t sAf = s0;
        const uint32_t sBf = s0 + A_SZ;

        #pragma unroll
        for (int ks = 0; ks < 2; ks++) {
            const int kb = ks * 16;
            uint32_t ah[4][4];
            #pragma unroll
            for (int mt = 0; mt < 4; mt++) {
                uint32_t off = (uint32_t)(((wm + mt * 16 + a_row) * ASTR + kb + a_col) * 2);
                ldm4(ah[mt], sAf + off);
            }
            #pragma unroll
            for (int p = 0; p < 4; p++) {
                uint32_t bf[4];
                uint32_t off = (uint32_t)(((wn + p * 16 + b_row) * ASTR + kb + b_col) * 2);
                ldm4(bf, sBf + off);
                #pragma unroll
                for (int mt = 0; mt < 4; mt++) {
                    #pragma unroll
                    for (int half = 0; half < 2; half++) {
                        int nt = p * 2 + half, si = half * 2;
                        mma16816(acc[mt][nt], ah[mt], bf[si], bf[si + 1]);
                    }
                }
            }
        }

        if (it + 2 < NIT) {
            int ns = stage + 2;
            if (ns >= 3) ns -= 3;
            issue(ns, (it + 2) * 32);
        }
        stage = (stage + 1 == 3) ? 0 : stage + 1;
    }

    if (!fused) {
        #pragma unroll
        for (int mt = 0; mt < 4; mt++)
            #pragma unroll
            for (int nt = 0; nt < 8; nt++) {
                int row = row0 + wm + mt * 16 + (lane >> 2);
                int col = col0 + wn + nt * 8 + (lane & 3) * 2;
                *(float2*)(C + (size_t)row * N + col) =
                    make_float2(acc[mt][nt][0], acc[mt][nt][1]);
                *(float2*)(C + (size_t)(row + 8) * N + col) =
                    make_float2(acc[mt][nt][2], acc[mt][nt][3]);
            }
        return;
    }

    // ---- fused QKV epilogue.  Warp tile = 64 cols = one head.
    const int gcol   = col0 + wn;           // multiple of 64
    const int region = gcol >> 10;          // 0=q, 1=k, 2=v
    const int dcol   = gcol & 1023;

    #pragma unroll
    for (int mt = 0; mt < 4; mt++) {
        float s0f = 1.f, s1f = 1.f;
        if (region < 2) {
            float ss0 = 0.f, ss1 = 0.f;
            #pragma unroll
            for (int nt = 0; nt < 8; nt++) {
                ss0 += acc[mt][nt][0] * acc[mt][nt][0]
                     + acc[mt][nt][1] * acc[mt][nt][1];
                ss1 += acc[mt][nt][2] * acc[mt][nt][2]
                     + acc[mt][nt][3] * acc[mt][nt][3];
            }
            ss0 += __shfl_xor_sync(0xffffffffu, ss0, 1);
            ss0 += __shfl_xor_sync(0xffffffffu, ss0, 2);
            ss1 += __shfl_xor_sync(0xffffffffu, ss1, 1);
            ss1 += __shfl_xor_sync(0xffffffffu, ss1, 2);
            s0f = 1.0f / fmaxf(sqrtf(ss0), 1e-12f);
            s1f = 1.0f / fmaxf(sqrtf(ss1), 1e-12f);
        }

        const int row = row0 + wm + mt * 16 + (lane >> 2);
        __half* dst = (region == 0) ? qf : (region == 1) ? kf : vf;
        #pragma unroll
        for (int nt = 0; nt < 8; nt++) {
            int col = dcol + nt * 8 + (lane & 3) * 2;
            size_t d0 = ((size_t)row * D_MODEL + col) / 2;
            size_t d1 = ((size_t)(row + 8) * D_MODEL + col) / 2;
            ((uint32_t*)dst)[d0] = pkh(acc[mt][nt][0] * s0f, acc[mt][nt][1] * s0f);
            ((uint32_t*)dst)[d1] = pkh(acc[mt][nt][2] * s1f, acc[mt][nt][3] * s1f);
        }
    }
}

// ---------------------------------------------------------------------------
// Tensor-core flash attention (causal, scale=8), fully 1-pass fp16.
// BM=64 (4 warps x m16), BN=64, DH=64, double-buffered K/V.
// Descending qb order (big tiles launch first).
// ---------------------------------------------------------------------------
#define VSTR 72
#define MATB (64 * VSTR * 2)          // 9216 bytes per matrix
#define FSTGB (2 * MATB)              // Kf + Vf per stage
#define FSMEM2 (2 * FSTGB)            // 36864

__global__ __launch_bounds__(128, 4) void flash_tc(
    const __half* __restrict__ qf,
    const __half* __restrict__ kf, const __half* __restrict__ vf,
    __half* __restrict__ of)
{
    extern __shared__ __align__(16) __half smx[];
    const uint32_t sb = smem_u32(smx);
    const int qb = (int)gridDim.x - 1 - (int)blockIdx.x;   // big tiles first
    const int head = blockIdx.y;
    const int t = threadIdx.x, w = t >> 5, lane = t & 31;
    const int hcol = head * DH;

    const int lr = t >> 1, lh = (t & 1) * 32;

    auto ldmat = [&](uint32_t base, const __half* m, int seq0) {
        const size_t g = (size_t)(seq0 + lr) * D_MODEL + hcol + lh;
        uint32_t d = base + (uint32_t)((lr * VSTR + lh) * 2);
        #pragma unroll
        for (int q2 = 0; q2 < 4; q2++)
            cp16(d + q2 * 16, m + g + q2 * 8);
    };

    // ---- stage Q through stage-0 slots, extract A-fragments
    ldmat(sb, qf, qb * 64);
    asm volatile("cp.async.commit_group;");
    asm volatile("cp.async.wait_group 0;");
    __syncthreads();

    const int a_row = (lane & 7) + (lane & 8);
    const int a_col = (lane >> 4) << 3;
    uint32_t ah[4][4];
    #pragma unroll
    for (int kc = 0; kc < 4; kc++) {
        uint32_t off = (uint32_t)(((w * 16 + a_row) * VSTR + kc * 16 + a_col) * 2);
        ldm4(ah[kc], sb + off);
    }
    __syncthreads();

    auto issue = [&](int stage, int jb) {
        uint32_t s0 = sb + (uint32_t)(stage * FSTGB);
        ldmat(s0,        kf, jb * 64);
        ldmat(s0 + MATB, vf, jb * 64);
        asm volatile("cp.async.commit_group;");
    };
    issue(0, 0);
    if (qb >= 1) issue(1, 1);

    float o[8][4];
    #pragma unroll
    for (int i = 0; i < 8; i++)
        #pragma unroll
        for (int j = 0; j < 4; j++) o[i][j] = 0.f;
    float m0 = -1e30f, m1 = -1e30f, l0 = 0.f, l1 = 0.f;

    const int b_row = (lane & 7) + ((lane & 16) >> 1);
    const int b_col = lane & 8;
    const int vg = lane >> 3;
    const int v_row = (vg & 1) * 8 + (lane & 7);
    const int v_col = (vg >> 1) * 8;
    const int myrow0 = qb * 64 + w * 16 + (lane >> 2);

    for (int jb = 0; jb <= qb; jb++) {
        if (jb < qb) asm volatile("cp.async.wait_group 1;");
        else         asm volatile("cp.async.wait_group 0;");
        __syncthreads();

        const uint32_t s0 = sb + (uint32_t)((jb & 1) * FSTGB);
        const uint32_t pKf = s0, pVf = s0 + MATB;

        float s[8][4];
        #pragma unroll
        for (int i = 0; i < 8; i++)
            #pragma unroll
            for (int j = 0; j < 4; j++) s[i][j] = 0.f;

        #pragma unroll
        for (int kc = 0; kc < 4; kc++) {
            uint32_t bh[4][4];
            #pragma unroll
            for (int p = 0; p < 4; p++) {
                uint32_t off = (uint32_t)(((p * 16 + b_row) * VSTR + kc * 16 + b_col) * 2);
                ldm4(bh[p], pKf + off);
            }
            #pragma unroll
            for (int nt = 0; nt < 8; nt++) {
                int p = nt >> 1, si = (nt & 1) * 2;
                mma16816(s[nt], ah[kc], bh[p][si], bh[p][si + 1]);
            }
        }

        if (jb == qb) {
            #pragma unroll
            for (int nt = 0; nt < 8; nt++) {
                int colb = jb * 64 + nt * 8 + (lane & 3) * 2;
                #pragma unroll
                for (int c = 0; c < 4; c++) {
                    int col = colb + (c & 1);
                    int row = myrow0 + (c >> 1) * 8;
                    s[nt][c] = (col > row) ? -1e30f : s[nt][c] * 8.0f;
                }
            }
        } else {
            #pragma unroll
            for (int nt = 0; nt < 8; nt++)
                #pragma unroll
                for (int c = 0; c < 4; c++) s[nt][c] *= 8.0f;
        }

        float mx0 = -1e30f, mx1 = -1e30f;
        #pragma unroll
        for (int nt = 0; nt < 8; nt++) {
            mx0 = fmaxf(mx0, fmaxf(s[nt][0], s[nt][1]));
            mx1 = fmaxf(mx1, fmaxf(s[nt][2], s[nt][3]));
        }
        mx0 = fmaxf(mx0, __shfl_xor_sync(0xffffffffu, mx0, 1));
        mx0 = fmaxf(mx0, __shfl_xor_sync(0xffffffffu, mx0, 2));
        mx1 = fmaxf(mx1, __shfl_xor_sync(0xffffffffu, mx1, 1));
        mx1 = fmaxf(mx1, __shfl_xor_sync(0xffffffffu, mx1, 2));
        float mn0 = fmaxf(m0, mx0), mn1 = fmaxf(m1, mx1);
        float c0 = __expf(m0 - mn0), c1 = __expf(m1 - mn1);
        m0 = mn0; m1 = mn1;

        float rs0 = 0.f, rs1 = 0.f;
        #pragma unroll
        for (int nt = 0; nt < 8; nt++) {
            s[nt][0] = __expf(s[nt][0] - mn0);
            s[nt][1] = __expf(s[nt][1] - mn0);
            s[nt][2] = __expf(s[nt][2] - mn1);
            s[nt][3] = __expf(s[nt][3] - mn1);
            rs0 += s[nt][0] + s[nt][1];
            rs1 += s[nt][2] + s[nt][3];
        }
        rs0 += __shfl_xor_sync(0xffffffffu, rs0, 1);
        rs0 += __shfl_xor_sync(0xffffffffu, rs0, 2);
        rs1 += __shfl_xor_sync(0xffffffffu, rs1, 1);
        rs1 += __shfl_xor_sync(0xffffffffu, rs1, 2);
        l0 = l0 * c0 + rs0;
        l1 = l1 * c1 + rs1;
        #pragma unroll
        for (int nt = 0; nt < 8; nt++) {
            o[nt][0] *= c0; o[nt][1] *= c0;
            o[nt][2] *= c1; o[nt][3] *= c1;
        }

        // ---- O += P V (1 pass): P rounded to fp16 in regs, V single fp16
        #pragma unroll
        for (int kt = 0; kt < 4; kt++) {
            uint32_t afh[4];
            #pragma unroll
            for (int hh = 0; hh < 2; hh++) {
                const float* sv = s[2 * kt + hh];
                afh[2 * hh]     = pkh(sv[0], sv[1]);
                afh[2 * hh + 1] = pkh(sv[2], sv[3]);
            }

            #pragma unroll
            for (int nc = 0; nc < 4; nc++) {
                uint32_t off = (uint32_t)(((kt * 16 + v_row) * VSTR + nc * 16 + v_col) * 2);
                uint32_t vb[4];
                ldm4t(vb, pVf + off);
                mma16816(o[2 * nc],     afh, vb[0], vb[1]);
                mma16816(o[2 * nc + 1], afh, vb[2], vb[3]);
            }
        }

        __syncthreads();
        if (jb + 2 <= qb) issue(jb & 1, jb + 2);
    }

    float inv0 = 1.0f / l0, inv1 = 1.0f / l1;
    #pragma unroll
    for (int nt = 0; nt < 8; nt++) {
        int col = hcol + nt * 8 + (lane & 3) * 2;
        {
            float x = o[nt][0] * inv0, y = o[nt][1] * inv0;
            size_t d = ((size_t)myrow0 * D_MODEL + col) / 2;
            ((uint32_t*)of)[d] = pkh(x, y);
        }
        {
            float x = o[nt][2] * inv1, y = o[nt][3] * inv1;
            size_t d = ((size_t)(myrow0 + 8) * D_MODEL + col) / 2;
            ((uint32_t*)of)[d] = pkh(x, y);
        }
    }
}

// ---------------------------------------------------------------------------
extern "C" void kernel_launch(void* const* d_in, const int* in_sizes, int n_in,
                              void* d_out, int out_size)
{
    const float* x  = (const float*)d_in[0];
    const float* Wq = (const float*)d_in[1];
    const float* Wk = (const float*)d_in[2];
    const float* Wv = (const float*)d_in[3];
    const float* Wo = (const float*)d_in[4];

    __half *xf, *qf, *kf, *vf, *of, *wf, *wof;
    cudaGetSymbolAddress((void**)&xf,  g_xf);
    cudaGetSymbolAddress((void**)&qf,  g_qf);
    cudaGetSymbolAddress((void**)&kf,  g_kf);
    cudaGetSymbolAddress((void**)&vf,  g_vf);
    cudaGetSymbolAddress((void**)&of,  g_of);
    cudaGetSymbolAddress((void**)&wf,  g_wf);
    cudaGetSymbolAddress((void**)&wof, g_wof);

    cudaFuncSetAttribute(gemm_fp16,
                         cudaFuncAttributeMaxDynamicSharedMemorySize, GSMEM);
    cudaFuncSetAttribute(flash_tc,
                         cudaFuncAttributeMaxDynamicSharedMemorySize, FSMEM2);

    const int NE4 = NSEQ * D_MODEL / 4;

    conv_kernel<<<NE4 / 256, 256>>>(x, xf);
    tconv4_kernel<<<dim3(D_MODEL / 32, D_MODEL / 32, 4), dim3(32, 8)>>>(
        Wq, Wk, Wv, Wo, wf, wof);

    // fused QKV GEMM (1-pass) + l2norm + fp16 epilogue
    gemm_fp16<<<dim3(D3 / 256, NSEQ / 128), 256, GSMEM>>>(
        xf, wf, nullptr, qf, kf, vf, NSEQ, D3, D_MODEL, 1);

    flash_tc<<<dim3(NSEQ / 64, HEADS), 128, FSMEM2>>>(qf, kf, vf, of);

    // out-proj (1-pass)
    gemm_fp16<<<dim3(D_MODEL / 256, NSEQ / 128), 256, GSMEM>>>(
        of, wof, (float*)d_out, nullptr, nullptr, nullptr,
        NSEQ, D_MODEL, D_MODEL, 0);
}

// round 17
// speedup vs baseline: 2.7156x; 1.0382x over previous
#include <cuda_runtime.h>
#include <cuda_fp16.h>
#include <math.h>
#include <stdint.h>

#define D_MODEL 1024
#define D3      3072
#define NSEQ    4096
#define HEADS   16
#define DH      64

// Scratch (allocation-free rule: __device__ globals)
__device__ __half g_xf [NSEQ * D_MODEL];
__device__ __half g_qf [NSEQ * D_MODEL];
__device__ __half g_kf [NSEQ * D_MODEL];
__device__ __half g_vf [NSEQ * D_MODEL];
__device__ __half g_of [NSEQ * D_MODEL];
__device__ __half g_wf [D3 * D_MODEL];              // Wqkv^T fp16 [N][K] concat
__device__ __half g_wof[D_MODEL * D_MODEL];         // Wo^T fp16

__device__ __forceinline__ uint32_t smem_u32(const void* p) {
    uint32_t a;
    asm("{ .reg .u64 t; cvta.to.shared.u64 t, %1; cvt.u32.u64 %0, t; }"
        : "=r"(a) : "l"(p));
    return a;
}

__device__ __forceinline__ void ldm4(uint32_t r[4], uint32_t addr) {
    asm volatile("ldmatrix.sync.aligned.m8n8.x4.shared.b16 {%0,%1,%2,%3}, [%4];"
                 : "=r"(r[0]), "=r"(r[1]), "=r"(r[2]), "=r"(r[3]) : "r"(addr));
}

__device__ __forceinline__ void ldm4t(uint32_t r[4], uint32_t addr) {
    asm volatile("ldmatrix.sync.aligned.m8n8.x4.trans.shared.b16 {%0,%1,%2,%3}, [%4];"
                 : "=r"(r[0]), "=r"(r[1]), "=r"(r[2]), "=r"(r[3]) : "r"(addr));
}

__device__ __forceinline__ void mma16816(float d[4], const uint32_t a[4],
                                         uint32_t b0, uint32_t b1) {
    asm volatile(
        "mma.sync.aligned.m16n8k16.row.col.f32.f16.f16.f32 "
        "{%0,%1,%2,%3}, {%4,%5,%6,%7}, {%8,%9}, {%0,%1,%2,%3};"
        : "+f"(d[0]), "+f"(d[1]), "+f"(d[2]), "+f"(d[3])
        : "r"(a[0]), "r"(a[1]), "r"(a[2]), "r"(a[3]), "r"(b0), "r"(b1));
}

__device__ __forceinline__ void cp16(uint32_t dst, const void* src) {
    asm volatile("cp.async.cg.shared.global [%0], [%1], 16;"
                 :: "r"(dst), "l"(src));
}

__device__ __forceinline__ uint32_t pkh(float x, float y) {
    __half2 h = __floats2half2_rn(x, y);
    return *(uint32_t*)&h;
}

// ---------------------------------------------------------------------------
// convert: fp32 -> fp16, 4 elements / thread.
// ---------------------------------------------------------------------------
__global__ void conv_kernel(const float* __restrict__ in,
                            __half* __restrict__ out)
{
    int i = blockIdx.x * blockDim.x + threadIdx.x;
    float4 v = ((const float4*)in)[i];
    ((uint2*)out)[i] = make_uint2(pkh(v.x, v.y), pkh(v.z, v.w));
}

// ---------------------------------------------------------------------------
// fused transpose-convert of all 4 weights (z selects matrix) to fp16.
// ---------------------------------------------------------------------------
__global__ void tconv4_kernel(const float* __restrict__ Wq,
                              const float* __restrict__ Wk,
                              const float* __restrict__ Wv,
                              const float* __restrict__ Wo,
                              __half* __restrict__ wf, __half* __restrict__ wof)
{
    __shared__ float tile[32][33];
    const int z = blockIdx.z;
    const float* W = (z == 0) ? Wq : (z == 1) ? Wk : (z == 2) ? Wv : Wo;
    __half* dh = (z == 3) ? wof : wf + (size_t)z * D_MODEL * D_MODEL;

    const int n0 = blockIdx.x * 32, k0 = blockIdx.y * 32;
    const int tx = threadIdx.x, ty = threadIdx.y;   // 32 x 8
    #pragma unroll
    for (int j = 0; j < 4; j++)
        tile[ty + 8 * j][tx] = W[(size_t)(k0 + ty + 8 * j) * D_MODEL + n0 + tx];
    __syncthreads();
    #pragma unroll
    for (int j = 0; j < 4; j++) {
        float v = tile[tx][ty + 8 * j];
        dh[(size_t)(n0 + ty + 8 * j) * D_MODEL + k0 + tx] = __float2half_rn(v);
    }
}

// ---------------------------------------------------------------------------
// Pipelined 1-pass fp16 GEMM.  C = Af @ Bf^T.
// CTA 128x256, BK=32, 8 warps (2x4, warp tile 64x64), 3-stage cp.async.
// fused=1: QKV epilogue — per-head l2norm of q,k and direct fp16 stores.
// ---------------------------------------------------------------------------
#define ASTR 40
#define A_SZ (128 * ASTR * 2)                 // 10240 bytes for Af
#define B_SZ (256 * ASTR * 2)                 // 20480 bytes for Bf
#define STG_B (A_SZ + B_SZ)                   // 30720
#define GSMEM (3 * STG_B)                     // 92160

__global__ __launch_bounds__(256, 1) void gemm_fp16(
    const __half* __restrict__ Af, const __half* __restrict__ Bf,
    float* __restrict__ C,
    __half* __restrict__ qf, __half* __restrict__ kf, __half* __restrict__ vf,
    int M, int N, int K, int fused)
{
    extern __shared__ __align__(16) __half smg[];
    const uint32_t sb = smem_u32(smg);
    const int t = threadIdx.x;
    const int wid = t >> 5, lane = t & 31;
    const int row0 = blockIdx.y * 128, col0 = blockIdx.x * 256;
    const int wm = (wid >> 2) * 64;    // 0 / 64
    const int wn = (wid & 3) * 64;     // 0..192

    const int r_c = t >> 2, c_c = t & 3;   // cp.async coords

    float acc[4][8][4];
    #pragma unroll
    for (int i = 0; i < 4; i++)
        #pragma unroll
        for (int j = 0; j < 8; j++)
            #pragma unroll
            for (int q = 0; q < 4; q++) acc[i][j][q] = 0.f;

    auto issue = [&](int stage, int k0) {
        uint32_t s0 = sb + (uint32_t)(stage * STG_B);
        #pragma unroll
        for (int h = 0; h < 2; h++) {
            int r = r_c + h * 64;
            uint32_t o = (uint32_t)((r * ASTR + c_c * 8) * 2);
            cp16(s0 + o, Af + (size_t)(row0 + r) * K + k0 + c_c * 8);
        }
        #pragma unroll
        for (int h = 0; h < 4; h++) {
            int r = r_c + h * 64;
            uint32_t o = (uint32_t)((r * ASTR + c_c * 8) * 2);
            cp16(s0 + A_SZ + o, Bf + (size_t)(col0 + r) * K + k0 + c_c * 8);
        }
        asm volatile("cp.async.commit_group;");
    };

    issue(0, 0);
    issue(1, 32);

    const int a_row = (lane & 7) + (lane & 8);
    const int a_col = (lane >> 4) << 3;
    const int b_row = (lane & 7) + ((lane & 16) >> 1);
    const int b_col = lane & 8;

    const int NIT = K >> 5;          // 32
    int stage = 0;
    for (int it = 0; it < NIT; it++) {
        asm volatile("cp.async.wait_group 1;");
        __syncthreads();

        const uint32_t s0 = sb + (uint32_t)(stage * STG_B);
        const uint32_t sAf = s0;
        const uint32_t sBf = s0 + A_SZ;

        #pragma unroll
        for (int ks = 0; ks < 2; ks++) {
            const int kb = ks * 16;
            uint32_t ah[4][4];
            #pragma unroll
            for (int mt = 0; mt < 4; mt++) {
                uint32_t off = (uint32_t)(((wm + mt * 16 + a_row) * ASTR + kb + a_col) * 2);
                ldm4(ah[mt], sAf + off);
            }
            #pragma unroll
            for (int p = 0; p < 4; p++) {
                uint32_t bf[4];
                uint32_t off = (uint32_t)(((wn + p * 16 + b_row) * ASTR + kb + b_col) * 2);
                ldm4(bf, sBf + off);
                #pragma unroll
                for (int mt = 0; mt < 4; mt++) {
                    #pragma unroll
                    for (int half = 0; half < 2; half++) {
                        int nt = p * 2 + half, si = half * 2;
                        mma16816(acc[mt][nt], ah[mt], bf[si], bf[si + 1]);
                    }
                }
            }
        }

        if (it + 2 < NIT) {
            int ns = stage + 2;
            if (ns >= 3) ns -= 3;
            issue(ns, (it + 2) * 32);
        }
        stage = (stage + 1 == 3) ? 0 : stage + 1;
    }

    if (!fused) {
        #pragma unroll
        for (int mt = 0; mt < 4; mt++)
            #pragma unroll
            for (int nt = 0; nt < 8; nt++) {
                int row = row0 + wm + mt * 16 + (lane >> 2);
                int col = col0 + wn + nt * 8 + (lane & 3) * 2;
                *(float2*)(C + (size_t)row * N + col) =
                    make_float2(acc[mt][nt][0], acc[mt][nt][1]);
                *(float2*)(C + (size_t)(row + 8) * N + col) =
                    make_float2(acc[mt][nt][2], acc[mt][nt][3]);
            }
        return;
    }

    // ---- fused QKV epilogue.  Warp tile = 64 cols = one head.
    const int gcol   = col0 + wn;           // multiple of 64
    const int region = gcol >> 10;          // 0=q, 1=k, 2=v
    const int dcol   = gcol & 1023;

    #pragma unroll
    for (int mt = 0; mt < 4; mt++) {
        float s0f = 1.f, s1f = 1.f;
        if (region < 2) {
            float ss0 = 0.f, ss1 = 0.f;
            #pragma unroll
            for (int nt = 0; nt < 8; nt++) {
                ss0 += acc[mt][nt][0] * acc[mt][nt][0]
                     + acc[mt][nt][1] * acc[mt][nt][1];
                ss1 += acc[mt][nt][2] * acc[mt][nt][2]
                     + acc[mt][nt][3] * acc[mt][nt][3];
            }
            ss0 += __shfl_xor_sync(0xffffffffu, ss0, 1);
            ss0 += __shfl_xor_sync(0xffffffffu, ss0, 2);
            ss1 += __shfl_xor_sync(0xffffffffu, ss1, 1);
            ss1 += __shfl_xor_sync(0xffffffffu, ss1, 2);
            s0f = 1.0f / fmaxf(sqrtf(ss0), 1e-12f);
            s1f = 1.0f / fmaxf(sqrtf(ss1), 1e-12f);
        }

        const int row = row0 + wm + mt * 16 + (lane >> 2);
        __half* dst = (region == 0) ? qf : (region == 1) ? kf : vf;
        #pragma unroll
        for (int nt = 0; nt < 8; nt++) {
            int col = dcol + nt * 8 + (lane & 3) * 2;
            size_t d0 = ((size_t)row * D_MODEL + col) / 2;
            size_t d1 = ((size_t)(row + 8) * D_MODEL + col) / 2;
            ((uint32_t*)dst)[d0] = pkh(acc[mt][nt][0] * s0f, acc[mt][nt][1] * s0f);
            ((uint32_t*)dst)[d1] = pkh(acc[mt][nt][2] * s1f, acc[mt][nt][3] * s1f);
        }
    }
}

// ---------------------------------------------------------------------------
// Tensor-core flash attention (causal, scale=8), 1-pass fp16.
// Logits bounded: s = 8*cos(q,k) in [-8,8] -> softmax with CONSTANT shift 0
// (no online max, no accumulator rescale).  P = exp(s) in [0, e^8], fp16-safe.
// BM=64 (4 warps x m16), BN=64, DH=64, double-buffered K/V, descending qb.
// ---------------------------------------------------------------------------
#define VSTR 72
#define MATB (64 * VSTR * 2)          // 9216 bytes per matrix
#define FSTGB (2 * MATB)              // Kf + Vf per stage
#define FSMEM2 (2 * FSTGB)            // 36864

__global__ __launch_bounds__(128, 4) void flash_tc(
    const __half* __restrict__ qf,
    const __half* __restrict__ kf, const __half* __restrict__ vf,
    __half* __restrict__ of)
{
    extern __shared__ __align__(16) __half smx[];
    const uint32_t sb = smem_u32(smx);
    const int qb = (int)gridDim.x - 1 - (int)blockIdx.x;   // big tiles first
    const int head = blockIdx.y;
    const int t = threadIdx.x, w = t >> 5, lane = t & 31;
    const int hcol = head * DH;

    const int lr = t >> 1, lh = (t & 1) * 32;

    auto ldmat = [&](uint32_t base, const __half* m, int seq0) {
        const size_t g = (size_t)(seq0 + lr) * D_MODEL + hcol + lh;
        uint32_t d = base + (uint32_t)((lr * VSTR + lh) * 2);
        #pragma unroll
        for (int q2 = 0; q2 < 4; q2++)
            cp16(d + q2 * 16, m + g + q2 * 8);
    };

    // ---- stage Q through stage-0 slots, extract A-fragments
    ldmat(sb, qf, qb * 64);
    asm volatile("cp.async.commit_group;");
    asm volatile("cp.async.wait_group 0;");
    __syncthreads();

    const int a_row = (lane & 7) + (lane & 8);
    const int a_col = (lane >> 4) << 3;
    uint32_t ah[4][4];
    #pragma unroll
    for (int kc = 0; kc < 4; kc++) {
        uint32_t off = (uint32_t)(((w * 16 + a_row) * VSTR + kc * 16 + a_col) * 2);
        ldm4(ah[kc], sb + off);
    }
    __syncthreads();

    auto issue = [&](int stage, int jb) {
        uint32_t s0 = sb + (uint32_t)(stage * FSTGB);
        ldmat(s0,        kf, jb * 64);
        ldmat(s0 + MATB, vf, jb * 64);
        asm volatile("cp.async.commit_group;");
    };
    issue(0, 0);
    if (qb >= 1) issue(1, 1);

    float o[8][4];
    #pragma unroll
    for (int i = 0; i < 8; i++)
        #pragma unroll
        for (int j = 0; j < 4; j++) o[i][j] = 0.f;
    float l0 = 0.f, l1 = 0.f;

    const int b_row = (lane & 7) + ((lane & 16) >> 1);
    const int b_col = lane & 8;
    const int vg = lane >> 3;
    const int v_row = (vg & 1) * 8 + (lane & 7);
    const int v_col = (vg >> 1) * 8;
    const int myrow0 = qb * 64 + w * 16 + (lane >> 2);

    for (int jb = 0; jb <= qb; jb++) {
        if (jb < qb) asm volatile("cp.async.wait_group 1;");
        else         asm volatile("cp.async.wait_group 0;");
        __syncthreads();

        const uint32_t s0 = sb + (uint32_t)((jb & 1) * FSTGB);
        const uint32_t pKf = s0, pVf = s0 + MATB;

        float s[8][4];
        #pragma unroll
        for (int i = 0; i < 8; i++)
            #pragma unroll
            for (int j = 0; j < 4; j++) s[i][j] = 0.f;

        #pragma unroll
        for (int kc = 0; kc < 4; kc++) {
            uint32_t bh[4][4];
            #pragma unroll
            for (int p = 0; p < 4; p++) {
                uint32_t off = (uint32_t)(((p * 16 + b_row) * VSTR + kc * 16 + b_col) * 2);
                ldm4(bh[p], pKf + off);
            }
            #pragma unroll
            for (int nt = 0; nt < 8; nt++) {
                int p = nt >> 1, si = (nt & 1) * 2;
                mma16816(s[nt], ah[kc], bh[p][si], bh[p][si + 1]);
            }
        }

        // ---- P = exp(8*s) (constant-shift softmax; logits bounded by 8)
        if (jb == qb) {
            #pragma unroll
            for (int nt = 0; nt < 8; nt++) {
                int colb = jb * 64 + nt * 8 + (lane & 3) * 2;
                #pragma unroll
                for (int c = 0; c < 4; c++) {
                    int col = colb + (c & 1);
                    int row = myrow0 + (c >> 1) * 8;
                    s[nt][c] = (col > row) ? 0.f : __expf(s[nt][c] * 8.0f);
                }
            }
        } else {
            #pragma unroll
            for (int nt = 0; nt < 8; nt++)
                #pragma unroll
                for (int c = 0; c < 4; c++)
                    s[nt][c] = __expf(s[nt][c] * 8.0f);
        }

        // ---- l += row sums
        float rs0 = 0.f, rs1 = 0.f;
        #pragma unroll
        for (int nt = 0; nt < 8; nt++) {
            rs0 += s[nt][0] + s[nt][1];
            rs1 += s[nt][2] + s[nt][3];
        }
        l0 += rs0;
        l1 += rs1;

        // ---- O += P V (1 pass): P rounded to fp16 in regs, V single fp16
        #pragma unroll
        for (int kt = 0; kt < 4; kt++) {
            uint32_t afh[4];
            #pragma unroll
            for (int hh = 0; hh < 2; hh++) {
                const float* sv = s[2 * kt + hh];
                afh[2 * hh]     = pkh(sv[0], sv[1]);
                afh[2 * hh + 1] = pkh(sv[2], sv[3]);
            }

            #pragma unroll
            for (int nc = 0; nc < 4; nc++) {
                uint32_t off = (uint32_t)(((kt * 16 + v_row) * VSTR + nc * 16 + v_col) * 2);
                uint32_t vb[4];
                ldm4t(vb, pVf + off);
                mma16816(o[2 * nc],     afh, vb[0], vb[1]);
                mma16816(o[2 * nc + 1], afh, vb[2], vb[3]);
            }
        }

        __syncthreads();
        if (jb + 2 <= qb) issue(jb & 1, jb + 2);
    }

    // ---- finalize: reduce l across the 4-lane row group, normalize, store
    l0 += __shfl_xor_sync(0xffffffffu, l0, 1);
    l0 += __shfl_xor_sync(0xffffffffu, l0, 2);
    l1 += __shfl_xor_sync(0xffffffffu, l1, 1);
    l1 += __shfl_xor_sync(0xffffffffu, l1, 2);
    float inv0 = 1.0f / l0, inv1 = 1.0f / l1;
    #pragma unroll
    for (int nt = 0; nt < 8; nt++) {
        int col = hcol + nt * 8 + (lane & 3) * 2;
        {
            float x = o[nt][0] * inv0, y = o[nt][1] * inv0;
            size_t d = ((size_t)myrow0 * D_MODEL + col) / 2;
            ((uint32_t*)of)[d] = pkh(x, y);
        }
        {
            float x = o[nt][2] * inv1, y = o[nt][3] * inv1;
            size_t d = ((size_t)(myrow0 + 8) * D_MODEL + col) / 2;
            ((uint32_t*)of)[d] = pkh(x, y);
        }
    }
}

// ---------------------------------------------------------------------------
extern "C" void kernel_launch(void* const* d_in, const int* in_sizes, int n_in,
                              void* d_out, int out_size)
{
    const float* x  = (const float*)d_in[0];
    const float* Wq = (const float*)d_in[1];
    const float* Wk = (const float*)d_in[2];
    const float* Wv = (const float*)d_in[3];
    const float* Wo = (const float*)d_in[4];

    __half *xf, *qf, *kf, *vf, *of, *wf, *wof;
    cudaGetSymbolAddress((void**)&xf,  g_xf);
    cudaGetSymbolAddress((void**)&qf,  g_qf);
    cudaGetSymbolAddress((void**)&kf,  g_kf);
    cudaGetSymbolAddress((void**)&vf,  g_vf);
    cudaGetSymbolAddress((void**)&of,  g_of);
    cudaGetSymbolAddress((void**)&wf,  g_wf);
    cudaGetSymbolAddress((void**)&wof, g_wof);

    cudaFuncSetAttribute(gemm_fp16,
                         cudaFuncAttributeMaxDynamicSharedMemorySize, GSMEM);
    cudaFuncSetAttribute(flash_tc,
                         cudaFuncAttributeMaxDynamicSharedMemorySize, FSMEM2);

    const int NE4 = NSEQ * D_MODEL / 4;

    conv_kernel<<<NE4 / 256, 256>>>(x, xf);
    tconv4_kernel<<<dim3(D_MODEL / 32, D_MODEL / 32, 4), dim3(32, 8)>>>(
        Wq, Wk, Wv, Wo, wf, wof);

    // fused QKV GEMM (1-pass) + l2norm + fp16 epilogue
    gemm_fp16<<<dim3(D3 / 256, NSEQ / 128), 256, GSMEM>>>(
        xf, wf, nullptr, qf, kf, vf, NSEQ, D3, D_MODEL, 1);

    flash_tc<<<dim3(NSEQ / 64, HEADS), 128, FSMEM2>>>(qf, kf, vf, of);

    // out-proj (1-pass)
    gemm_fp16<<<dim3(D_MODEL / 256, NSEQ / 128), 256, GSMEM>>>(
        of, wof, (float*)d_out, nullptr, nullptr, nullptr,
        NSEQ, D_MODEL, D_MODEL, 0);
}